// round 1
// baseline (speedup 1.0000x reference)
#include <cuda_runtime.h>
#include <math.h>

// ---------------- problem constants ----------------
#define D_    768
#define H_    12
#define HD_   64
#define FF_   3072
#define SEQ_  197
#define B_    32
#define NTOK  (B_ * SEQ_)     // 6304
#define L_    12
#define E_    512
#define NP_   196             // patches per image
#define IMG_  224
#define P_    16

// ---------------- device scratch (no allocation allowed) ----------------
__device__ float g_patch[B_ * NP_ * D_];     // im2col patches   [6272, 768]
__device__ float g_x[NTOK * D_];             // residual stream  [6304, 768]
__device__ float g_ln[NTOK * D_];            // LN output        [6304, 768]
__device__ float g_qkv[NTOK * 3 * D_];       // qkv              [6304, 2304]
__device__ float g_att[NTOK * D_];           // attn out / patch-gemm temp
__device__ float g_ff[NTOK * FF_];           // MLP hidden       [6304, 3072]

// ---------------- reductions ----------------
__device__ __forceinline__ void block_sum2(float& a, float& b, float* sm) {
    // sm must hold >= 16 floats; blockDim.x multiple of 32, <= 256
    #pragma unroll
    for (int o = 16; o; o >>= 1) {
        a += __shfl_xor_sync(0xffffffffu, a, o);
        b += __shfl_xor_sync(0xffffffffu, b, o);
    }
    int warp = threadIdx.x >> 5, lane = threadIdx.x & 31;
    int nw = blockDim.x >> 5;
    if (lane == 0) { sm[warp] = a; sm[warp + 8] = b; }
    __syncthreads();
    if (threadIdx.x == 0) {
        float sa = 0.f, sb = 0.f;
        for (int i = 0; i < nw; i++) { sa += sm[i]; sb += sm[i + 8]; }
        sm[0] = sa; sm[8] = sb;
    }
    __syncthreads();
    a = sm[0]; b = sm[8];
    __syncthreads();
}

__device__ __forceinline__ float block_max(float v, float* sm) {
    #pragma unroll
    for (int o = 16; o; o >>= 1) v = fmaxf(v, __shfl_xor_sync(0xffffffffu, v, o));
    int warp = threadIdx.x >> 5, lane = threadIdx.x & 31;
    int nw = blockDim.x >> 5;
    if (lane == 0) sm[warp] = v;
    __syncthreads();
    if (threadIdx.x == 0) {
        float m = sm[0];
        for (int i = 1; i < nw; i++) m = fmaxf(m, sm[i]);
        sm[0] = m;
    }
    __syncthreads();
    v = sm[0];
    __syncthreads();
    return v;
}

__device__ __forceinline__ float block_sum(float v, float* sm) {
    #pragma unroll
    for (int o = 16; o; o >>= 1) v += __shfl_xor_sync(0xffffffffu, v, o);
    int warp = threadIdx.x >> 5, lane = threadIdx.x & 31;
    int nw = blockDim.x >> 5;
    if (lane == 0) sm[warp] = v;
    __syncthreads();
    if (threadIdx.x == 0) {
        float s = 0.f;
        for (int i = 0; i < nw; i++) s += sm[i];
        sm[0] = s;
    }
    __syncthreads();
    v = sm[0];
    __syncthreads();
    return v;
}

// ---------------- patchify (im2col gather) ----------------
__global__ void patchify_kernel(const float* __restrict__ img) {
    int idx = blockIdx.x * 256 + threadIdx.x;
    if (idx >= B_ * NP_ * D_) return;
    int k = idx % D_;
    int bp = idx / D_;
    int p = bp % NP_;
    int b = bp / NP_;
    int c = k >> 8;            // 256 = 16*16
    int rem = k & 255;
    int dy = rem >> 4, dx = rem & 15;
    int y = (p / 14) * P_ + dy;
    int x = (p % 14) * P_ + dx;
    g_patch[idx] = img[(((size_t)b * 3 + c) * IMG_ + y) * IMG_ + x];
}

// ---------------- generic NT SGEMM: C = A[M,K] * Bw[N,K]^T (+bias, epilogue) ----
// MODE 0: C = acc + bias
// MODE 1: C = res + acc + bias   (residual add)
// MODE 2: C = gelu(acc + bias)   (exact erf gelu)
__device__ __forceinline__ float gelu_exact(float v) {
    return 0.5f * v * (1.0f + erff(v * 0.70710678118654752f));
}

template <int MODE>
__global__ void __launch_bounds__(256) gemm_nt(
    const float* __restrict__ A, const float* __restrict__ Bw,
    const float* __restrict__ bias, const float* __restrict__ res,
    float* __restrict__ C, int M, int N, int K)
{
    __shared__ float As[16][68];
    __shared__ float Bs[16][68];
    int tid = threadIdx.x;
    int tx = tid & 15, ty = tid >> 4;
    int row0 = blockIdx.x * 64, col0 = blockIdx.y * 64;

    float acc[4][4] = {};

    int lm = tid >> 2;            // 0..63 : tile row for loads
    int lk = (tid & 3) * 4;       // 0,4,8,12 : k offset for float4 load
    int arow = row0 + lm;
    int brow = col0 + lm;         // N is always a multiple of 64 here
    const float* Ap = A + (size_t)arow * K + lk;
    const float* Bp = Bw + (size_t)brow * K + lk;
    bool aval = (arow < M);

    for (int k0 = 0; k0 < K; k0 += 16) {
        float4 av = aval ? *(const float4*)(Ap + k0) : make_float4(0.f, 0.f, 0.f, 0.f);
        float4 bv = *(const float4*)(Bp + k0);
        As[lk + 0][lm] = av.x; As[lk + 1][lm] = av.y;
        As[lk + 2][lm] = av.z; As[lk + 3][lm] = av.w;
        Bs[lk + 0][lm] = bv.x; Bs[lk + 1][lm] = bv.y;
        Bs[lk + 2][lm] = bv.z; Bs[lk + 3][lm] = bv.w;
        __syncthreads();
        #pragma unroll
        for (int kk = 0; kk < 16; kk++) {
            float4 a4 = *((const float4*)As[kk] + ty);
            float4 b4 = *((const float4*)Bs[kk] + tx);
            float a[4] = {a4.x, a4.y, a4.z, a4.w};
            float bb[4] = {b4.x, b4.y, b4.z, b4.w};
            #pragma unroll
            for (int i = 0; i < 4; i++)
                #pragma unroll
                for (int j = 0; j < 4; j++)
                    acc[i][j] = fmaf(a[i], bb[j], acc[i][j]);
        }
        __syncthreads();
    }

    int cn = col0 + tx * 4;
    float4 bias4 = make_float4(0.f, 0.f, 0.f, 0.f);
    if (bias) bias4 = *(const float4*)(bias + cn);
    #pragma unroll
    for (int i = 0; i < 4; i++) {
        int r = row0 + ty * 4 + i;
        if (r >= M) break;
        float4 v;
        v.x = acc[i][0] + bias4.x;
        v.y = acc[i][1] + bias4.y;
        v.z = acc[i][2] + bias4.z;
        v.w = acc[i][3] + bias4.w;
        if (MODE == 1) {
            float4 rv = *(const float4*)(res + (size_t)r * N + cn);
            v.x += rv.x; v.y += rv.y; v.z += rv.z; v.w += rv.w;
        }
        if (MODE == 2) {
            v.x = gelu_exact(v.x); v.y = gelu_exact(v.y);
            v.z = gelu_exact(v.z); v.w = gelu_exact(v.w);
        }
        *(float4*)(C + (size_t)r * N + cn) = v;
    }
}

// ---------------- embed + ln_pre: build residual stream ----------------
__global__ void __launch_bounds__(256) embed_ln_kernel(
    const float* __restrict__ cls_emb, const float* __restrict__ pos_emb,
    const float* __restrict__ w, const float* __restrict__ bb)
{
    __shared__ float sm[16];
    int row = blockIdx.x;             // token index b*SEQ + s
    int b = row / SEQ_, s = row % SEQ_;
    int tid = threadIdx.x;
    float v[3];
    #pragma unroll
    for (int i = 0; i < 3; i++) {
        int d = tid + i * 256;
        float base = (s == 0) ? cls_emb[d]
                              : g_att[((size_t)(b * NP_ + (s - 1))) * D_ + d];
        v[i] = base + pos_emb[(size_t)s * D_ + d];
    }
    float sum = v[0] + v[1] + v[2];
    float sq = v[0] * v[0] + v[1] * v[1] + v[2] * v[2];
    block_sum2(sum, sq, sm);
    float mean = sum * (1.0f / D_);
    float var = sq * (1.0f / D_) - mean * mean;
    float r = rsqrtf(var + 1e-5f);
    #pragma unroll
    for (int i = 0; i < 3; i++) {
        int d = tid + i * 256;
        g_x[(size_t)row * D_ + d] = (v[i] - mean) * r * w[d] + bb[d];
    }
}

// ---------------- generic layernorm ----------------
__global__ void __launch_bounds__(256) ln_kernel(
    const float* __restrict__ x, float* __restrict__ y,
    const float* __restrict__ w, const float* __restrict__ bb)
{
    __shared__ float sm[16];
    int row = blockIdx.x;
    int tid = threadIdx.x;
    const float* xr = x + (size_t)row * D_;
    float v[3];
    #pragma unroll
    for (int i = 0; i < 3; i++) v[i] = xr[tid + i * 256];
    float sum = v[0] + v[1] + v[2];
    float sq = v[0] * v[0] + v[1] * v[1] + v[2] * v[2];
    block_sum2(sum, sq, sm);
    float mean = sum * (1.0f / D_);
    float var = sq * (1.0f / D_) - mean * mean;
    float r = rsqrtf(var + 1e-5f);
    float* yr = y + (size_t)row * D_;
    #pragma unroll
    for (int i = 0; i < 3; i++) {
        int d = tid + i * 256;
        yr[d] = (v[i] - mean) * r * w[d] + bb[d];
    }
}

// ---------------- fused attention: one block per (head-batch, query row) ----
__global__ void __launch_bounds__(128) attn_kernel() {
    __shared__ float qs[HD_];
    __shared__ float sc[SEQ_];
    __shared__ float part[HD_];
    __shared__ float sm[16];
    int s = blockIdx.x;
    int bh = blockIdx.y;
    int b = bh / H_, h = bh % H_;
    int tid = threadIdx.x;
    const float scale = 0.125f;   // 1/sqrt(64)

    size_t base = (size_t)(b * SEQ_) * (3 * D_) + (size_t)h * HD_;
    const float* qrow = g_qkv + base + (size_t)s * (3 * D_);
    if (tid < HD_) qs[tid] = qrow[tid] * scale;
    __syncthreads();

    // scores
    for (int t = tid; t < SEQ_; t += 128) {
        const float* kr = g_qkv + base + (size_t)t * (3 * D_) + D_;
        float a = 0.f;
        #pragma unroll
        for (int d = 0; d < HD_; d += 4) {
            float4 kv = *(const float4*)(kr + d);
            a += qs[d] * kv.x + qs[d + 1] * kv.y + qs[d + 2] * kv.z + qs[d + 3] * kv.w;
        }
        sc[t] = a;
    }
    __syncthreads();

    // softmax
    float mx = -1e30f;
    for (int t = tid; t < SEQ_; t += 128) mx = fmaxf(mx, sc[t]);
    mx = block_max(mx, sm);
    float lsum = 0.f;
    for (int t = tid; t < SEQ_; t += 128) {
        float e = expf(sc[t] - mx);
        sc[t] = e;
        lsum += e;
    }
    lsum = block_sum(lsum, sm);
    float inv = 1.0f / lsum;
    __syncthreads();

    // o = p @ V  (two halves of the block cover even/odd t, then combine)
    int d = tid & 63, half = tid >> 6;
    const float* vp = g_qkv + base + 2 * D_ + d + (size_t)half * (3 * D_);
    float acc = 0.f;
    for (int t = half; t < SEQ_; t += 2, vp += 2 * (3 * D_)) acc += sc[t] * vp[0];
    if (half) part[d] = acc;
    __syncthreads();
    if (!half)
        g_att[((size_t)(b * SEQ_ + s)) * D_ + h * HD_ + d] = (acc + part[d]) * inv;
}

// ---------------- final head: ln_post(cls) @ proj, L2-normalize ----------------
__global__ void __launch_bounds__(256) head_kernel(
    const float* __restrict__ w, const float* __restrict__ bb,
    const float* __restrict__ proj, float* __restrict__ out)
{
    __shared__ float cls[D_];
    __shared__ float feats[E_];
    __shared__ float sm[16];
    int b = blockIdx.x;
    int tid = threadIdx.x;
    const float* xr = g_x + (size_t)(b * SEQ_) * D_;   // cls token = s 0
    float v[3];
    #pragma unroll
    for (int i = 0; i < 3; i++) v[i] = xr[tid + i * 256];
    float sum = v[0] + v[1] + v[2];
    float sq = v[0] * v[0] + v[1] * v[1] + v[2] * v[2];
    block_sum2(sum, sq, sm);
    float mean = sum * (1.0f / D_);
    float var = sq * (1.0f / D_) - mean * mean;
    float r = rsqrtf(var + 1e-5f);
    #pragma unroll
    for (int i = 0; i < 3; i++) {
        int d = tid + i * 256;
        cls[d] = (v[i] - mean) * r * w[d] + bb[d];
    }
    __syncthreads();
    for (int e = tid; e < E_; e += 256) {
        float a = 0.f;
        for (int d = 0; d < D_; d++) a += cls[d] * proj[(size_t)d * E_ + e];
        feats[e] = a;
    }
    __syncthreads();
    float nrm = 0.f;
    for (int e = tid; e < E_; e += 256) nrm += feats[e] * feats[e];
    nrm = block_sum(nrm, sm);
    float rn = rsqrtf(nrm);
    for (int e = tid; e < E_; e += 256) out[(size_t)b * E_ + e] = feats[e] * rn;
}

// ---------------- host ----------------
extern "C" void kernel_launch(void* const* d_in, const int* in_sizes, int n_in,
                              void* d_out, int out_size)
{
    const float* image     = (const float*)d_in[0];
    const float* conv_w    = (const float*)d_in[1];
    const float* cls_emb   = (const float*)d_in[2];
    const float* pos_emb   = (const float*)d_in[3];
    const float* ln_pre_w  = (const float*)d_in[4];
    const float* ln_pre_b  = (const float*)d_in[5];
    const float* ln1_w     = (const float*)d_in[6];
    const float* ln1_b     = (const float*)d_in[7];
    const float* qkv_w     = (const float*)d_in[8];
    const float* qkv_b     = (const float*)d_in[9];
    const float* out_w     = (const float*)d_in[10];
    const float* out_b     = (const float*)d_in[11];
    const float* ln2_w     = (const float*)d_in[12];
    const float* ln2_b     = (const float*)d_in[13];
    const float* fc_w      = (const float*)d_in[14];
    const float* fc_b      = (const float*)d_in[15];
    const float* pr_w      = (const float*)d_in[16];
    const float* pr_b      = (const float*)d_in[17];
    const float* ln_post_w = (const float*)d_in[18];
    const float* ln_post_b = (const float*)d_in[19];
    const float* proj      = (const float*)d_in[20];
    float* out = (float*)d_out;
    (void)in_sizes; (void)n_in; (void)out_size;

    float *p_patch, *p_x, *p_ln, *p_qkv, *p_att, *p_ff;
    cudaGetSymbolAddress((void**)&p_patch, g_patch);
    cudaGetSymbolAddress((void**)&p_x,     g_x);
    cudaGetSymbolAddress((void**)&p_ln,    g_ln);
    cudaGetSymbolAddress((void**)&p_qkv,   g_qkv);
    cudaGetSymbolAddress((void**)&p_att,   g_att);
    cudaGetSymbolAddress((void**)&p_ff,    g_ff);

    // patchify + conv-as-GEMM -> g_att (temp)
    patchify_kernel<<<(B_ * NP_ * D_ + 255) / 256, 256>>>(image);
    gemm_nt<0><<<dim3(98, 12), 256>>>(p_patch, conv_w, nullptr, nullptr,
                                      p_att, B_ * NP_, D_, D_);
    // cls + pos + ln_pre -> g_x
    embed_ln_kernel<<<NTOK, 256>>>(cls_emb, pos_emb, ln_pre_w, ln_pre_b);

    const int MT = (NTOK + 63) / 64;   // 99
    for (int l = 0; l < L_; l++) {
        ln_kernel<<<NTOK, 256>>>(p_x, p_ln, ln1_w + l * D_, ln1_b + l * D_);
        gemm_nt<0><<<dim3(MT, 36), 256>>>(p_ln, qkv_w + (size_t)l * 3 * D_ * D_,
                                          qkv_b + (size_t)l * 3 * D_, nullptr,
                                          p_qkv, NTOK, 3 * D_, D_);
        attn_kernel<<<dim3(SEQ_, B_ * H_), 128>>>();
        gemm_nt<1><<<dim3(MT, 12), 256>>>(p_att, out_w + (size_t)l * D_ * D_,
                                          out_b + (size_t)l * D_, p_x,
                                          p_x, NTOK, D_, D_);
        ln_kernel<<<NTOK, 256>>>(p_x, p_ln, ln2_w + l * D_, ln2_b + l * D_);
        gemm_nt<2><<<dim3(MT, 48), 256>>>(p_ln, fc_w + (size_t)l * FF_ * D_,
                                          fc_b + (size_t)l * FF_, nullptr,
                                          p_ff, NTOK, FF_, D_);
        gemm_nt<1><<<dim3(MT, 12), 256>>>(p_ff, pr_w + (size_t)l * D_ * FF_,
                                          pr_b + (size_t)l * D_, p_x,
                                          p_x, NTOK, D_, FF_);
    }
    head_kernel<<<B_, 256>>>(ln_post_w, ln_post_b, proj, out);
}

// round 3
// speedup vs baseline: 2.9345x; 2.9345x over previous
#include <cuda_runtime.h>
#include <math.h>
#include <stdint.h>

// ---------------- problem constants ----------------
#define D_    768
#define H_    12
#define HD_   64
#define FF_   3072
#define SEQ_  197
#define B_    32
#define NTOK  (B_ * SEQ_)     // 6304
#define MP_   6400            // padded token rows (50 * 128)
#define L_    12
#define E_    512
#define NP_   196
#define IMG_  224
#define P_    16

// ---------------- device scratch (no allocation allowed) ----------------
__device__ float g_patch[MP_ * D_];
__device__ float g_x[MP_ * D_];
__device__ float g_ln[MP_ * D_];
__device__ float g_qkv[MP_ * 3 * D_];
__device__ float g_att[MP_ * D_];
__device__ float g_ff[MP_ * FF_];
// tf32-rounded weight copies
__device__ float w_qkv[L_ * 3 * D_ * D_];
__device__ float w_out[L_ * D_ * D_];
__device__ float w_fc[L_ * FF_ * D_];
__device__ float w_pr[L_ * D_ * FF_];
__device__ float w_conv[D_ * D_];

// ---------------- helpers ----------------
__device__ __forceinline__ float tf32_rna(float x) {
    uint32_t r;
    asm("cvt.rna.tf32.f32 %0, %1;" : "=r"(r) : "f"(x));
    return __uint_as_float(r);
}
__device__ __forceinline__ float gelu_exact(float v) {
    return 0.5f * v * (1.0f + erff(v * 0.70710678118654752f));
}
#define CP_ASYNC16(dst, src) \
    asm volatile("cp.async.cg.shared.global [%0], [%1], 16;\n" :: "r"(dst), "l"(src))
#define CP_COMMIT() asm volatile("cp.async.commit_group;\n" ::: "memory")
#define CP_WAIT0()  asm volatile("cp.async.wait_group 0;\n" ::: "memory")

__device__ __forceinline__ uint32_t smem_u32(const void* p) {
    uint32_t a;
    asm("{ .reg .u64 t; cvta.to.shared.u64 t, %1; cvt.u32.u64 %0, t; }" : "=r"(a) : "l"(p));
    return a;
}
__device__ __forceinline__ void mma_tf32(float* c, const uint32_t* a, const uint32_t* b) {
    asm volatile(
        "mma.sync.aligned.m16n8k8.row.col.f32.tf32.tf32.f32 "
        "{%0,%1,%2,%3}, {%4,%5,%6,%7}, {%8,%9}, {%0,%1,%2,%3};"
        : "+f"(c[0]), "+f"(c[1]), "+f"(c[2]), "+f"(c[3])
        : "r"(a[0]), "r"(a[1]), "r"(a[2]), "r"(a[3]), "r"(b[0]), "r"(b[1]));
}

// ---------------- tf32-rounding copy (weights) ----------------
__global__ void rna4_kernel(const float4* __restrict__ s, float4* __restrict__ d, int n4) {
    int i = blockIdx.x * 256 + threadIdx.x;
    if (i >= n4) return;
    float4 v = s[i];
    v.x = tf32_rna(v.x); v.y = tf32_rna(v.y); v.z = tf32_rna(v.z); v.w = tf32_rna(v.w);
    d[i] = v;
}

// ---------------- tf32 tensor-core GEMM: C = A[M,K] * W[N,K]^T ----------------
// block tile 128x128x32, 8 warps, each warp 64x32 (4x4 m16n8k8 tiles)
// MODE 0: C = acc + bias ; MODE 1: C = res + acc + bias ; MODE 2: C = gelu(acc + bias)
#define LDK 36                       // padded smem row stride (floats)
#define TILE_F (128 * LDK)           // floats per buffer
#define GSMEM_BYTES (4 * TILE_F * 4) // A[2] + B[2]

template <int MODE, bool RNA>
__global__ void __launch_bounds__(256) gemm_tc(
    const float* __restrict__ A, const float* __restrict__ W,
    const float* __restrict__ bias, const float* __restrict__ res,
    float* __restrict__ C, int N, int K)
{
    extern __shared__ float smem[];
    float* As = smem;                 // [2][128][LDK]
    float* Bs = smem + 2 * TILE_F;    // [2][128][LDK]

    int tid = threadIdx.x;
    int wid = tid >> 5, lane = tid & 31;
    int g = lane >> 2, t = lane & 3;
    int warpM = wid & 1, warpN = wid >> 1;      // 2 x 4 warp grid

    int row0 = blockIdx.x * 128;
    int col0 = blockIdx.y * 128;
    const float* Abase = A + (size_t)row0 * K;
    const float* Wbase = W + (size_t)col0 * K;

    // gmem->smem chunk mapping: 1024 16B-chunks per tile, 4 per thread
    int cr = tid >> 1;                 // rows   tid/2*? -> use idx scheme below
    (void)cr;

    float acc[4][4][4];
    #pragma unroll
    for (int i = 0; i < 4; i++)
        #pragma unroll
        for (int j = 0; j < 4; j++)
            #pragma unroll
            for (int r = 0; r < 4; r++) acc[i][j][r] = 0.f;

    uint32_t sA = smem_u32(As);
    uint32_t sB = smem_u32(Bs);

    auto load_tile = [&](int buf, int k0) {
        uint32_t offA = sA + buf * TILE_F * 4;
        uint32_t offB = sB + buf * TILE_F * 4;
        #pragma unroll
        for (int i = 0; i < 4; i++) {
            int idx = tid + i * 256;          // 0..1023
            int r = idx >> 3, c = idx & 7;    // row, 16B chunk
            uint32_t d = (uint32_t)(r * LDK + c * 4) * 4u;
            CP_ASYNC16(offA + d, Abase + (size_t)r * K + k0 + c * 4);
            CP_ASYNC16(offB + d, Wbase + (size_t)r * K + k0 + c * 4);
        }
        CP_COMMIT();
    };

    int nIter = K >> 5;
    load_tile(0, 0);
    CP_WAIT0();
    __syncthreads();

    for (int it = 0; it < nIter; it++) {
        int buf = it & 1;
        if (it + 1 < nIter) load_tile(buf ^ 1, (it + 1) << 5);

        const float* Ab = As + buf * TILE_F;
        const float* Bb = Bs + buf * TILE_F;
        int arow = warpM * 64 + g;
        int brow = warpN * 32 + g;
        #pragma unroll
        for (int kt = 0; kt < 4; kt++) {
            int k0 = kt * 8 + t;
            uint32_t af[4][4], bf[4][2];
            #pragma unroll
            for (int mt = 0; mt < 4; mt++) {
                const float* p = Ab + (arow + mt * 16) * LDK + k0;
                af[mt][0] = __float_as_uint(p[0]);
                af[mt][1] = __float_as_uint(p[8 * LDK]);
                af[mt][2] = __float_as_uint(p[4]);
                af[mt][3] = __float_as_uint(p[8 * LDK + 4]);
            }
            #pragma unroll
            for (int nt = 0; nt < 4; nt++) {
                const float* p = Bb + (brow + nt * 8) * LDK + k0;
                bf[nt][0] = __float_as_uint(p[0]);
                bf[nt][1] = __float_as_uint(p[4]);
            }
            #pragma unroll
            for (int mt = 0; mt < 4; mt++)
                #pragma unroll
                for (int nt = 0; nt < 4; nt++)
                    mma_tf32(acc[mt][nt], af[mt], bf[nt]);
        }
        if (it + 1 < nIter) {
            CP_WAIT0();
            __syncthreads();
        }
    }

    // ---------------- epilogue ----------------
    #pragma unroll
    for (int nt = 0; nt < 4; nt++) {
        int col = col0 + warpN * 32 + nt * 8 + 2 * t;
        float2 bv = make_float2(0.f, 0.f);
        if (bias) bv = *(const float2*)(bias + col);
        #pragma unroll
        for (int mt = 0; mt < 4; mt++) {
            int row = row0 + warpM * 64 + mt * 16 + g;
            #pragma unroll
            for (int half = 0; half < 2; half++) {
                int r = row + half * 8;
                float2 v;
                v.x = acc[mt][nt][half * 2 + 0] + bv.x;
                v.y = acc[mt][nt][half * 2 + 1] + bv.y;
                if (MODE == 1) {
                    float2 rv = *(const float2*)(res + (size_t)r * N + col);
                    v.x += rv.x; v.y += rv.y;
                }
                if (MODE == 2) { v.x = gelu_exact(v.x); v.y = gelu_exact(v.y); }
                if (RNA) { v.x = tf32_rna(v.x); v.y = tf32_rna(v.y); }
                *(float2*)(C + (size_t)r * N + col) = v;
            }
        }
    }
}

// ---------------- patchify (im2col gather, tf32-rounded) ----------------
__global__ void patchify_kernel(const float* __restrict__ img) {
    int idx = blockIdx.x * 256 + threadIdx.x;
    if (idx >= B_ * NP_ * D_) return;
    int k = idx % D_;
    int bp = idx / D_;
    int p = bp % NP_;
    int b = bp / NP_;
    int c = k >> 8;
    int rem = k & 255;
    int dy = rem >> 4, dx = rem & 15;
    int y = (p / 14) * P_ + dy;
    int x = (p % 14) * P_ + dx;
    g_patch[idx] = tf32_rna(img[(((size_t)b * 3 + c) * IMG_ + y) * IMG_ + x]);
}

// ---------------- reductions ----------------
__device__ __forceinline__ void block_sum2(float& a, float& b, float* sm) {
    #pragma unroll
    for (int o = 16; o; o >>= 1) {
        a += __shfl_xor_sync(0xffffffffu, a, o);
        b += __shfl_xor_sync(0xffffffffu, b, o);
    }
    int warp = threadIdx.x >> 5, lane = threadIdx.x & 31;
    int nw = blockDim.x >> 5;
    if (lane == 0) { sm[warp] = a; sm[warp + 8] = b; }
    __syncthreads();
    if (threadIdx.x == 0) {
        float sa = 0.f, sb = 0.f;
        for (int i = 0; i < nw; i++) { sa += sm[i]; sb += sm[i + 8]; }
        sm[0] = sa; sm[8] = sb;
    }
    __syncthreads();
    a = sm[0]; b = sm[8];
    __syncthreads();
}
__device__ __forceinline__ float block_sum(float v, float* sm) {
    #pragma unroll
    for (int o = 16; o; o >>= 1) v += __shfl_xor_sync(0xffffffffu, v, o);
    int warp = threadIdx.x >> 5, lane = threadIdx.x & 31;
    int nw = blockDim.x >> 5;
    if (lane == 0) sm[warp] = v;
    __syncthreads();
    if (threadIdx.x == 0) {
        float s = 0.f;
        for (int i = 0; i < nw; i++) s += sm[i];
        sm[0] = s;
    }
    __syncthreads();
    v = sm[0];
    __syncthreads();
    return v;
}

// ---------------- embed + ln_pre ----------------
__global__ void __launch_bounds__(256) embed_ln_kernel(
    const float* __restrict__ cls_emb, const float* __restrict__ pos_emb,
    const float* __restrict__ w, const float* __restrict__ bb)
{
    __shared__ float sm[16];
    int row = blockIdx.x;
    int b = row / SEQ_, s = row % SEQ_;
    int tid = threadIdx.x;
    float v[3];
    #pragma unroll
    for (int i = 0; i < 3; i++) {
        int d = tid + i * 256;
        float base = (s == 0) ? cls_emb[d]
                              : g_att[((size_t)(b * NP_ + (s - 1))) * D_ + d];
        v[i] = base + pos_emb[(size_t)s * D_ + d];
    }
    float sum = v[0] + v[1] + v[2];
    float sq = v[0] * v[0] + v[1] * v[1] + v[2] * v[2];
    block_sum2(sum, sq, sm);
    float mean = sum * (1.0f / D_);
    float var = sq * (1.0f / D_) - mean * mean;
    float r = rsqrtf(var + 1e-5f);
    #pragma unroll
    for (int i = 0; i < 3; i++) {
        int d = tid + i * 256;
        g_x[(size_t)row * D_ + d] = (v[i] - mean) * r * w[d] + bb[d];
    }
}

// ---------------- layernorm (output tf32-rounded: feeds GEMM A) ----------------
__global__ void __launch_bounds__(256) ln_kernel(
    const float* __restrict__ x, float* __restrict__ y,
    const float* __restrict__ w, const float* __restrict__ bb)
{
    __shared__ float sm[16];
    int row = blockIdx.x;
    int tid = threadIdx.x;
    const float* xr = x + (size_t)row * D_;
    float v[3];
    #pragma unroll
    for (int i = 0; i < 3; i++) v[i] = xr[tid + i * 256];
    float sum = v[0] + v[1] + v[2];
    float sq = v[0] * v[0] + v[1] * v[1] + v[2] * v[2];
    block_sum2(sum, sq, sm);
    float mean = sum * (1.0f / D_);
    float var = sq * (1.0f / D_) - mean * mean;
    float r = rsqrtf(var + 1e-5f);
    float* yr = y + (size_t)row * D_;
    #pragma unroll
    for (int i = 0; i < 3; i++) {
        int d = tid + i * 256;
        yr[d] = tf32_rna((v[i] - mean) * r * w[d] + bb[d]);
    }
}

// ---------------- attention v2: 32 queries per block, K/V tiled in smem ------
#define TQ_ 32
__global__ void __launch_bounds__(256) attn2_kernel() {
    __shared__ __align__(16) float Ks[64][68];
    __shared__ __align__(16) float sc[TQ_][200];
    int q0 = blockIdx.x * TQ_;
    int bh = blockIdx.y;
    int b = bh / H_, h = bh % H_;
    int tid = threadIdx.x;
    size_t base = (size_t)(b * SEQ_) * (3 * D_) + (size_t)h * HD_;

    // stage Q (scaled), then keep in registers
    float* Qtmp = &sc[0][0];
    for (int i = tid; i < TQ_ * 16; i += 256) {
        int r = i >> 4, j = i & 15;
        int srow = q0 + r;
        float4 v = make_float4(0.f, 0.f, 0.f, 0.f);
        if (srow < SEQ_)
            v = *(const float4*)(g_qkv + base + (size_t)srow * (3 * D_) + j * 4);
        v.x *= 0.125f; v.y *= 0.125f; v.z *= 0.125f; v.w *= 0.125f;
        *(float4*)(Qtmp + r * 64 + j * 4) = v;
    }
    __syncthreads();
    int q = tid >> 3, toff = tid & 7;
    float4 rq[16];
    #pragma unroll
    for (int j = 0; j < 16; j++) rq[j] = *(const float4*)(Qtmp + q * 64 + j * 4);
    __syncthreads();

    // scores
    for (int t0 = 0; t0 < SEQ_; t0 += 64) {
        int len = min(64, SEQ_ - t0);
        for (int i = tid; i < len * 16; i += 256) {
            int r = i >> 4, j = i & 15;
            float4 kv = *(const float4*)(g_qkv + base + D_ + (size_t)(t0 + r) * (3 * D_) + j * 4);
            *(float4*)(&Ks[r][j * 4]) = kv;
        }
        __syncthreads();
        for (int tt = toff; tt < len; tt += 8) {
            float a = 0.f;
            #pragma unroll
            for (int j = 0; j < 16; j++) {
                float4 kv = *(const float4*)(&Ks[tt][j * 4]);
                a += rq[j].x * kv.x + rq[j].y * kv.y + rq[j].z * kv.z + rq[j].w * kv.w;
            }
            sc[q][t0 + tt] = a;
        }
        __syncthreads();
    }

    // softmax: warp w handles 4 rows
    {
        int lane = tid & 31, w = tid >> 5;
        for (int r = w * 4; r < w * 4 + 4; r++) {
            float mx = -1e30f;
            for (int tt = lane; tt < SEQ_; tt += 32) mx = fmaxf(mx, sc[r][tt]);
            #pragma unroll
            for (int o = 16; o; o >>= 1) mx = fmaxf(mx, __shfl_xor_sync(0xffffffffu, mx, o));
            float s = 0.f;
            for (int tt = lane; tt < SEQ_; tt += 32) {
                float e = expf(sc[r][tt] - mx);
                sc[r][tt] = e;
                s += e;
            }
            #pragma unroll
            for (int o = 16; o; o >>= 1) s += __shfl_xor_sync(0xffffffffu, s, o);
            float inv = 1.0f / s;
            for (int tt = lane; tt < SEQ_; tt += 32) sc[r][tt] *= inv;
        }
    }
    __syncthreads();

    // o = p @ V
    int dg = tid & 7;
    float4 a0 = make_float4(0.f, 0.f, 0.f, 0.f);
    float4 a1 = make_float4(0.f, 0.f, 0.f, 0.f);
    for (int t0 = 0; t0 < SEQ_; t0 += 64) {
        int len = min(64, SEQ_ - t0);
        for (int i = tid; i < len * 16; i += 256) {
            int r = i >> 4, j = i & 15;
            float4 vv = *(const float4*)(g_qkv + base + 2 * D_ + (size_t)(t0 + r) * (3 * D_) + j * 4);
            *(float4*)(&Ks[r][j * 4]) = vv;
        }
        __syncthreads();
        for (int tt = 0; tt < len; tt++) {
            float p = sc[q][t0 + tt];
            float4 v0 = *(const float4*)(&Ks[tt][dg * 8]);
            float4 v1 = *(const float4*)(&Ks[tt][dg * 8 + 4]);
            a0.x += p * v0.x; a0.y += p * v0.y; a0.z += p * v0.z; a0.w += p * v0.w;
            a1.x += p * v1.x; a1.y += p * v1.y; a1.z += p * v1.z; a1.w += p * v1.w;
        }
        __syncthreads();
    }
    int srow = q0 + q;
    if (srow < SEQ_) {
        float* o = g_att + (size_t)(b * SEQ_ + srow) * D_ + h * HD_ + dg * 8;
        a0.x = tf32_rna(a0.x); a0.y = tf32_rna(a0.y); a0.z = tf32_rna(a0.z); a0.w = tf32_rna(a0.w);
        a1.x = tf32_rna(a1.x); a1.y = tf32_rna(a1.y); a1.z = tf32_rna(a1.z); a1.w = tf32_rna(a1.w);
        *(float4*)o = a0;
        *(float4*)(o + 4) = a1;
    }
}

// ---------------- final head ----------------
__global__ void __launch_bounds__(256) head_kernel(
    const float* __restrict__ w, const float* __restrict__ bb,
    const float* __restrict__ proj, float* __restrict__ out)
{
    __shared__ float cls[D_];
    __shared__ float feats[E_];
    __shared__ float sm[16];
    int b = blockIdx.x;
    int tid = threadIdx.x;
    const float* xr = g_x + (size_t)(b * SEQ_) * D_;
    float v[3];
    #pragma unroll
    for (int i = 0; i < 3; i++) v[i] = xr[tid + i * 256];
    float sum = v[0] + v[1] + v[2];
    float sq = v[0] * v[0] + v[1] * v[1] + v[2] * v[2];
    block_sum2(sum, sq, sm);
    float mean = sum * (1.0f / D_);
    float var = sq * (1.0f / D_) - mean * mean;
    float r = rsqrtf(var + 1e-5f);
    #pragma unroll
    for (int i = 0; i < 3; i++) {
        int d = tid + i * 256;
        cls[d] = (v[i] - mean) * r * w[d] + bb[d];
    }
    __syncthreads();
    for (int e = tid; e < E_; e += 256) {
        float a = 0.f;
        for (int d = 0; d < D_; d++) a += cls[d] * proj[(size_t)d * E_ + e];
        feats[e] = a;
    }
    __syncthreads();
    float nrm = 0.f;
    for (int e = tid; e < E_; e += 256) nrm += feats[e] * feats[e];
    nrm = block_sum(nrm, sm);
    float rn = rsqrtf(nrm);
    for (int e = tid; e < E_; e += 256) out[(size_t)b * E_ + e] = feats[e] * rn;
}

// ---------------- host ----------------
extern "C" void kernel_launch(void* const* d_in, const int* in_sizes, int n_in,
                              void* d_out, int out_size)
{
    const float* image     = (const float*)d_in[0];
    const float* conv_w    = (const float*)d_in[1];
    const float* cls_emb   = (const float*)d_in[2];
    const float* pos_emb   = (const float*)d_in[3];
    const float* ln_pre_w  = (const float*)d_in[4];
    const float* ln_pre_b  = (const float*)d_in[5];
    const float* ln1_w     = (const float*)d_in[6];
    const float* ln1_b     = (const float*)d_in[7];
    const float* qkv_w     = (const float*)d_in[8];
    const float* qkv_b     = (const float*)d_in[9];
    const float* out_w     = (const float*)d_in[10];
    const float* out_b     = (const float*)d_in[11];
    const float* ln2_w     = (const float*)d_in[12];
    const float* ln2_b     = (const float*)d_in[13];
    const float* fc_w      = (const float*)d_in[14];
    const float* fc_b      = (const float*)d_in[15];
    const float* pr_w      = (const float*)d_in[16];
    const float* pr_b      = (const float*)d_in[17];
    const float* ln_post_w = (const float*)d_in[18];
    const float* ln_post_b = (const float*)d_in[19];
    const float* proj      = (const float*)d_in[20];
    float* out = (float*)d_out;
    (void)in_sizes; (void)n_in; (void)out_size;

    float *p_patch, *p_x, *p_ln, *p_qkv, *p_att, *p_ff;
    float *pw_qkv, *pw_out, *pw_fc, *pw_pr, *pw_conv;
    cudaGetSymbolAddress((void**)&p_patch, g_patch);
    cudaGetSymbolAddress((void**)&p_x,     g_x);
    cudaGetSymbolAddress((void**)&p_ln,    g_ln);
    cudaGetSymbolAddress((void**)&p_qkv,   g_qkv);
    cudaGetSymbolAddress((void**)&p_att,   g_att);
    cudaGetSymbolAddress((void**)&p_ff,    g_ff);
    cudaGetSymbolAddress((void**)&pw_qkv,  w_qkv);
    cudaGetSymbolAddress((void**)&pw_out,  w_out);
    cudaGetSymbolAddress((void**)&pw_fc,   w_fc);
    cudaGetSymbolAddress((void**)&pw_pr,   w_pr);
    cudaGetSymbolAddress((void**)&pw_conv, w_conv);

    cudaFuncSetAttribute(gemm_tc<0, false>, cudaFuncAttributeMaxDynamicSharedMemorySize, GSMEM_BYTES);
    cudaFuncSetAttribute(gemm_tc<1, false>, cudaFuncAttributeMaxDynamicSharedMemorySize, GSMEM_BYTES);
    cudaFuncSetAttribute(gemm_tc<2, true>,  cudaFuncAttributeMaxDynamicSharedMemorySize, GSMEM_BYTES);

    // tf32-round the weights into scratch copies
    auto rna = [&](const float* s, float* d, int n) {
        rna4_kernel<<<(n / 4 + 255) / 256, 256>>>((const float4*)s, (float4*)d, n / 4);
    };
    rna(qkv_w, pw_qkv, L_ * 3 * D_ * D_);
    rna(out_w, pw_out, L_ * D_ * D_);
    rna(fc_w,  pw_fc,  L_ * FF_ * D_);
    rna(pr_w,  pw_pr,  L_ * D_ * FF_);
    rna(conv_w, pw_conv, D_ * D_);

    const int MT = MP_ / 128;   // 50

    // patchify + conv-as-GEMM -> g_att
    patchify_kernel<<<(B_ * NP_ * D_ + 255) / 256, 256>>>(image);
    gemm_tc<0, false><<<dim3(MT, D_ / 128), 256, GSMEM_BYTES>>>(
        p_patch, pw_conv, nullptr, nullptr, p_att, D_, D_);
    embed_ln_kernel<<<NTOK, 256>>>(cls_emb, pos_emb, ln_pre_w, ln_pre_b);

    for (int l = 0; l < L_; l++) {
        ln_kernel<<<NTOK, 256>>>(p_x, p_ln, ln1_w + l * D_, ln1_b + l * D_);
        gemm_tc<0, false><<<dim3(MT, 3 * D_ / 128), 256, GSMEM_BYTES>>>(
            p_ln, pw_qkv + (size_t)l * 3 * D_ * D_, qkv_b + (size_t)l * 3 * D_,
            nullptr, p_qkv, 3 * D_, D_);
        attn2_kernel<<<dim3((SEQ_ + TQ_ - 1) / TQ_, B_ * H_), 256>>>();
        gemm_tc<1, false><<<dim3(MT, D_ / 128), 256, GSMEM_BYTES>>>(
            p_att, pw_out + (size_t)l * D_ * D_, out_b + (size_t)l * D_,
            p_x, p_x, D_, D_);
        ln_kernel<<<NTOK, 256>>>(p_x, p_ln, ln2_w + l * D_, ln2_b + l * D_);
        gemm_tc<2, true><<<dim3(MT, FF_ / 128), 256, GSMEM_BYTES>>>(
            p_ln, pw_fc + (size_t)l * FF_ * D_, fc_b + (size_t)l * FF_,
            nullptr, p_ff, FF_, D_);
        gemm_tc<1, false><<<dim3(MT, D_ / 128), 256, GSMEM_BYTES>>>(
            p_ff, pw_pr + (size_t)l * D_ * FF_, pr_b + (size_t)l * D_,
            p_x, p_x, D_, FF_);
    }
    head_kernel<<<B_, 256>>>(ln_post_w, ln_post_b, proj, out);
}

// round 4
// speedup vs baseline: 2.9786x; 1.0150x over previous
#include <cuda_runtime.h>
#include <math.h>
#include <stdint.h>

// ---------------- problem constants ----------------
#define D_    768
#define H_    12
#define HD_   64
#define FF_   3072
#define SEQ_  197
#define B_    32
#define NTOK  (B_ * SEQ_)     // 6304
#define MP_   6400            // padded token rows (50 * 128)
#define L_    12
#define E_    512
#define NP_   196
#define IMG_  224
#define P_    16

// ---------------- device scratch (no allocation allowed) ----------------
__device__ float g_patch[MP_ * D_];
__device__ float g_x[MP_ * D_];
__device__ float g_ln[MP_ * D_];
__device__ float g_qkv[MP_ * 3 * D_];
__device__ float g_att[MP_ * D_];
__device__ float g_ff[MP_ * FF_];
// tf32-rounded weight copies
__device__ float w_qkv[L_ * 3 * D_ * D_];
__device__ float w_out[L_ * D_ * D_];
__device__ float w_fc[L_ * FF_ * D_];
__device__ float w_pr[L_ * D_ * FF_];
__device__ float w_conv[D_ * D_];

// ---------------- helpers ----------------
__device__ __forceinline__ float tf32_rna(float x) {
    uint32_t r;
    asm("cvt.rna.tf32.f32 %0, %1;" : "=r"(r) : "f"(x));
    return __uint_as_float(r);
}
__device__ __forceinline__ float gelu_exact(float v) {
    return 0.5f * v * (1.0f + erff(v * 0.70710678118654752f));
}
#define CP_ASYNC16(dst, src) \
    asm volatile("cp.async.cg.shared.global [%0], [%1], 16;\n" :: "r"(dst), "l"(src))
#define CP_COMMIT() asm volatile("cp.async.commit_group;\n" ::: "memory")
#define CP_WAIT1()  asm volatile("cp.async.wait_group 1;\n" ::: "memory")

__device__ __forceinline__ uint32_t smem_u32(const void* p) {
    uint32_t a;
    asm("{ .reg .u64 t; cvta.to.shared.u64 t, %1; cvt.u32.u64 %0, t; }" : "=r"(a) : "l"(p));
    return a;
}
__device__ __forceinline__ void mma_tf32(float* c, const uint32_t* a, const uint32_t* b) {
    asm volatile(
        "mma.sync.aligned.m16n8k8.row.col.f32.tf32.tf32.f32 "
        "{%0,%1,%2,%3}, {%4,%5,%6,%7}, {%8,%9}, {%0,%1,%2,%3};"
        : "+f"(c[0]), "+f"(c[1]), "+f"(c[2]), "+f"(c[3])
        : "r"(a[0]), "r"(a[1]), "r"(a[2]), "r"(a[3]), "r"(b[0]), "r"(b[1]));
}
#define LDSM4(r, a) \
    asm volatile("ldmatrix.sync.aligned.m8n8.x4.shared.b16 {%0,%1,%2,%3}, [%4];" \
        : "=r"((r)[0]), "=r"((r)[1]), "=r"((r)[2]), "=r"((r)[3]) : "r"(a))

// ---------------- tf32-rounding copy (weights) ----------------
__global__ void rna4_kernel(const float4* __restrict__ s, float4* __restrict__ d, int n4) {
    int i = blockIdx.x * 256 + threadIdx.x;
    if (i >= n4) return;
    float4 v = s[i];
    v.x = tf32_rna(v.x); v.y = tf32_rna(v.y); v.z = tf32_rna(v.z); v.w = tf32_rna(v.w);
    d[i] = v;
}

// ---------------- tf32 tensor-core GEMM: C = A[M,K] * W[N,K]^T ----------------
// block tile 128x256x32, 8 warps (2x4), warp tile 64x64
// 3-stage cp.async pipeline, XOR-swizzled smem, ldmatrix fragment loads
// MODE 0: C = acc + bias ; MODE 1: C = res + acc + bias ; MODE 2: C = gelu(acc + bias)
#define STAGE_BYTES 49152u          // A tile 16KB + B tile 32KB
#define GSMEM_BYTES (3 * 49152)

template <int MODE, bool RNA>
__global__ void __launch_bounds__(256) gemm_tc(
    const float* __restrict__ A, const float* __restrict__ W,
    const float* __restrict__ bias, const float* __restrict__ res,
    float* __restrict__ C, int N, int K)
{
    extern __shared__ float smem[];
    uint32_t sbase = smem_u32(smem);
    int tid = threadIdx.x;
    int wid = tid >> 5, lane = tid & 31;
    int g = lane >> 2, t = lane & 3;
    int warpM = wid & 1, warpN = wid >> 1;       // 2 x 4 warp grid

    int row0 = blockIdx.x * 128;
    int col0 = blockIdx.y * 256;
    const float* Abase = A + (size_t)row0 * K;
    const float* Wbase = W + (size_t)col0 * K;

    auto load_stage = [&](int s, int k0) {
        uint32_t ab = sbase + (uint32_t)s * STAGE_BYTES;
        uint32_t bb = ab + 16384u;
        #pragma unroll
        for (int i = 0; i < 4; i++) {
            int idx = tid + i * 256;
            int r = idx >> 3, c = idx & 7;
            uint32_t d = ab + (uint32_t)(r * 128 + ((c ^ (r & 7)) * 16));
            CP_ASYNC16(d, Abase + (size_t)r * K + k0 + c * 4);
        }
        #pragma unroll
        for (int i = 0; i < 8; i++) {
            int idx = tid + i * 256;
            int r = idx >> 3, c = idx & 7;
            uint32_t d = bb + (uint32_t)(r * 128 + ((c ^ (r & 7)) * 16));
            CP_ASYNC16(d, Wbase + (size_t)r * K + k0 + c * 4);
        }
        CP_COMMIT();
    };

    float acc[4][8][4];
    #pragma unroll
    for (int i = 0; i < 4; i++)
        #pragma unroll
        for (int j = 0; j < 8; j++)
            #pragma unroll
            for (int r = 0; r < 4; r++) acc[i][j][r] = 0.f;

    // ldmatrix per-lane address components
    int ar = lane & 15;                       // A fragment row within 16
    int asel = lane >> 4;                     // A chunk select (0/1)
    int brr = (lane & 7) + ((lane >> 4) << 3); // B fragment row within 16
    int bsel = (lane >> 3) & 1;               // B chunk select (0/1)
    uint32_t aRow[4], bRow[4], aChunk[4], bChunk[4];
    #pragma unroll
    for (int mt = 0; mt < 4; mt++)
        aRow[mt] = (uint32_t)((warpM * 64 + mt * 16 + ar) * 128);
    #pragma unroll
    for (int nt2 = 0; nt2 < 4; nt2++)
        bRow[nt2] = (uint32_t)((warpN * 64 + nt2 * 16 + brr) * 128);
    #pragma unroll
    for (int kt = 0; kt < 4; kt++) {
        aChunk[kt] = (uint32_t)((((kt * 2 + asel) ^ (lane & 7)) * 16));
        bChunk[kt] = (uint32_t)((((kt * 2 + bsel) ^ (lane & 7)) * 16));
    }

    int nIter = K >> 5;
    load_stage(0, 0);
    load_stage(1, 32);

    for (int it = 0; it < nIter; it++) {
        CP_WAIT1();
        __syncthreads();
        if (it + 2 < nIter) load_stage((it + 2) % 3, (it + 2) * 32);
        else CP_COMMIT();

        uint32_t ab = sbase + (uint32_t)(it % 3) * STAGE_BYTES;
        uint32_t bb = ab + 16384u;
        #pragma unroll
        for (int kt = 0; kt < 4; kt++) {
            uint32_t af[4][4], bf[4][4];
            #pragma unroll
            for (int mt = 0; mt < 4; mt++)
                LDSM4(af[mt], ab + aRow[mt] + aChunk[kt]);
            #pragma unroll
            for (int nt2 = 0; nt2 < 4; nt2++)
                LDSM4(bf[nt2], bb + bRow[nt2] + bChunk[kt]);
            #pragma unroll
            for (int mt = 0; mt < 4; mt++)
                #pragma unroll
                for (int nt2 = 0; nt2 < 4; nt2++) {
                    mma_tf32(acc[mt][nt2 * 2],     af[mt], &bf[nt2][0]);
                    mma_tf32(acc[mt][nt2 * 2 + 1], af[mt], &bf[nt2][2]);
                }
        }
    }

    // ---------------- epilogue ----------------
    #pragma unroll
    for (int nt = 0; nt < 8; nt++) {
        int col = col0 + warpN * 64 + nt * 8 + 2 * t;
        float2 bv = make_float2(0.f, 0.f);
        if (bias) bv = *(const float2*)(bias + col);
        #pragma unroll
        for (int mt = 0; mt < 4; mt++) {
            int row = row0 + warpM * 64 + mt * 16 + g;
            #pragma unroll
            for (int half = 0; half < 2; half++) {
                int r = row + half * 8;
                float2 v;
                v.x = acc[mt][nt][half * 2 + 0] + bv.x;
                v.y = acc[mt][nt][half * 2 + 1] + bv.y;
                if (MODE == 1) {
                    float2 rv = *(const float2*)(res + (size_t)r * N + col);
                    v.x += rv.x; v.y += rv.y;
                }
                if (MODE == 2) { v.x = gelu_exact(v.x); v.y = gelu_exact(v.y); }
                if (RNA) { v.x = tf32_rna(v.x); v.y = tf32_rna(v.y); }
                *(float2*)(C + (size_t)r * N + col) = v;
            }
        }
    }
}

// ---------------- patchify (im2col gather, tf32-rounded) ----------------
__global__ void patchify_kernel(const float* __restrict__ img) {
    int idx = blockIdx.x * 256 + threadIdx.x;
    if (idx >= B_ * NP_ * D_) return;
    int k = idx % D_;
    int bp = idx / D_;
    int p = bp % NP_;
    int b = bp / NP_;
    int c = k >> 8;
    int rem = k & 255;
    int dy = rem >> 4, dx = rem & 15;
    int y = (p / 14) * P_ + dy;
    int x = (p % 14) * P_ + dx;
    g_patch[idx] = tf32_rna(img[(((size_t)b * 3 + c) * IMG_ + y) * IMG_ + x]);
}

// ---------------- reductions ----------------
__device__ __forceinline__ void block_sum2(float& a, float& b, float* sm) {
    #pragma unroll
    for (int o = 16; o; o >>= 1) {
        a += __shfl_xor_sync(0xffffffffu, a, o);
        b += __shfl_xor_sync(0xffffffffu, b, o);
    }
    int warp = threadIdx.x >> 5, lane = threadIdx.x & 31;
    int nw = blockDim.x >> 5;
    if (lane == 0) { sm[warp] = a; sm[warp + 8] = b; }
    __syncthreads();
    if (threadIdx.x == 0) {
        float sa = 0.f, sb = 0.f;
        for (int i = 0; i < nw; i++) { sa += sm[i]; sb += sm[i + 8]; }
        sm[0] = sa; sm[8] = sb;
    }
    __syncthreads();
    a = sm[0]; b = sm[8];
    __syncthreads();
}
__device__ __forceinline__ float block_sum(float v, float* sm) {
    #pragma unroll
    for (int o = 16; o; o >>= 1) v += __shfl_xor_sync(0xffffffffu, v, o);
    int warp = threadIdx.x >> 5, lane = threadIdx.x & 31;
    int nw = blockDim.x >> 5;
    if (lane == 0) sm[warp] = v;
    __syncthreads();
    if (threadIdx.x == 0) {
        float s = 0.f;
        for (int i = 0; i < nw; i++) s += sm[i];
        sm[0] = s;
    }
    __syncthreads();
    v = sm[0];
    __syncthreads();
    return v;
}

// ---------------- embed + ln_pre ----------------
__global__ void __launch_bounds__(256) embed_ln_kernel(
    const float* __restrict__ cls_emb, const float* __restrict__ pos_emb,
    const float* __restrict__ w, const float* __restrict__ bb)
{
    __shared__ float sm[16];
    int row = blockIdx.x;
    int b = row / SEQ_, s = row % SEQ_;
    int tid = threadIdx.x;
    float v[3];
    #pragma unroll
    for (int i = 0; i < 3; i++) {
        int d = tid + i * 256;
        float base = (s == 0) ? cls_emb[d]
                              : g_att[((size_t)(b * NP_ + (s - 1))) * D_ + d];
        v[i] = base + pos_emb[(size_t)s * D_ + d];
    }
    float sum = v[0] + v[1] + v[2];
    float sq = v[0] * v[0] + v[1] * v[1] + v[2] * v[2];
    block_sum2(sum, sq, sm);
    float mean = sum * (1.0f / D_);
    float var = sq * (1.0f / D_) - mean * mean;
    float r = rsqrtf(var + 1e-5f);
    #pragma unroll
    for (int i = 0; i < 3; i++) {
        int d = tid + i * 256;
        g_x[(size_t)row * D_ + d] = (v[i] - mean) * r * w[d] + bb[d];
    }
}

// ---------------- layernorm (output tf32-rounded: feeds GEMM A) ----------------
__global__ void __launch_bounds__(256) ln_kernel(
    const float* __restrict__ x, float* __restrict__ y,
    const float* __restrict__ w, const float* __restrict__ bb)
{
    __shared__ float sm[16];
    int row = blockIdx.x;
    int tid = threadIdx.x;
    const float* xr = x + (size_t)row * D_;
    float v[3];
    #pragma unroll
    for (int i = 0; i < 3; i++) v[i] = xr[tid + i * 256];
    float sum = v[0] + v[1] + v[2];
    float sq = v[0] * v[0] + v[1] * v[1] + v[2] * v[2];
    block_sum2(sum, sq, sm);
    float mean = sum * (1.0f / D_);
    float var = sq * (1.0f / D_) - mean * mean;
    float r = rsqrtf(var + 1e-5f);
    float* yr = y + (size_t)row * D_;
    #pragma unroll
    for (int i = 0; i < 3; i++) {
        int d = tid + i * 256;
        yr[d] = tf32_rna((v[i] - mean) * r * w[d] + bb[d]);
    }
}

// ---------------- attention v2: 32 queries per block, K/V tiled in smem ------
#define TQ_ 32
__global__ void __launch_bounds__(256) attn2_kernel() {
    __shared__ __align__(16) float Ks[64][68];
    __shared__ __align__(16) float sc[TQ_][200];
    int q0 = blockIdx.x * TQ_;
    int bh = blockIdx.y;
    int b = bh / H_, h = bh % H_;
    int tid = threadIdx.x;
    size_t base = (size_t)(b * SEQ_) * (3 * D_) + (size_t)h * HD_;

    // stage Q (scaled), then keep in registers
    float* Qtmp = &sc[0][0];
    for (int i = tid; i < TQ_ * 16; i += 256) {
        int r = i >> 4, j = i & 15;
        int srow = q0 + r;
        float4 v = make_float4(0.f, 0.f, 0.f, 0.f);
        if (srow < SEQ_)
            v = *(const float4*)(g_qkv + base + (size_t)srow * (3 * D_) + j * 4);
        v.x *= 0.125f; v.y *= 0.125f; v.z *= 0.125f; v.w *= 0.125f;
        *(float4*)(Qtmp + r * 64 + j * 4) = v;
    }
    __syncthreads();
    int q = tid >> 3, toff = tid & 7;
    float4 rq[16];
    #pragma unroll
    for (int j = 0; j < 16; j++) rq[j] = *(const float4*)(Qtmp + q * 64 + j * 4);
    __syncthreads();

    // scores
    for (int t0 = 0; t0 < SEQ_; t0 += 64) {
        int len = min(64, SEQ_ - t0);
        for (int i = tid; i < len * 16; i += 256) {
            int r = i >> 4, j = i & 15;
            float4 kv = *(const float4*)(g_qkv + base + D_ + (size_t)(t0 + r) * (3 * D_) + j * 4);
            *(float4*)(&Ks[r][j * 4]) = kv;
        }
        __syncthreads();
        for (int tt = toff; tt < len; tt += 8) {
            float a = 0.f;
            #pragma unroll
            for (int j = 0; j < 16; j++) {
                float4 kv = *(const float4*)(&Ks[tt][j * 4]);
                a += rq[j].x * kv.x + rq[j].y * kv.y + rq[j].z * kv.z + rq[j].w * kv.w;
            }
            sc[q][t0 + tt] = a;
        }
        __syncthreads();
    }

    // softmax: warp w handles 4 rows
    {
        int lane = tid & 31, w = tid >> 5;
        for (int r = w * 4; r < w * 4 + 4; r++) {
            float mx = -1e30f;
            for (int tt = lane; tt < SEQ_; tt += 32) mx = fmaxf(mx, sc[r][tt]);
            #pragma unroll
            for (int o = 16; o; o >>= 1) mx = fmaxf(mx, __shfl_xor_sync(0xffffffffu, mx, o));
            float s = 0.f;
            for (int tt = lane; tt < SEQ_; tt += 32) {
                float e = expf(sc[r][tt] - mx);
                sc[r][tt] = e;
                s += e;
            }
            #pragma unroll
            for (int o = 16; o; o >>= 1) s += __shfl_xor_sync(0xffffffffu, s, o);
            float inv = 1.0f / s;
            for (int tt = lane; tt < SEQ_; tt += 32) sc[r][tt] *= inv;
        }
    }
    __syncthreads();

    // o = p @ V
    int dg = tid & 7;
    float4 a0 = make_float4(0.f, 0.f, 0.f, 0.f);
    float4 a1 = make_float4(0.f, 0.f, 0.f, 0.f);
    for (int t0 = 0; t0 < SEQ_; t0 += 64) {
        int len = min(64, SEQ_ - t0);
        for (int i = tid; i < len * 16; i += 256) {
            int r = i >> 4, j = i & 15;
            float4 vv = *(const float4*)(g_qkv + base + 2 * D_ + (size_t)(t0 + r) * (3 * D_) + j * 4);
            *(float4*)(&Ks[r][j * 4]) = vv;
        }
        __syncthreads();
        for (int tt = 0; tt < len; tt++) {
            float p = sc[q][t0 + tt];
            float4 v0 = *(const float4*)(&Ks[tt][dg * 8]);
            float4 v1 = *(const float4*)(&Ks[tt][dg * 8 + 4]);
            a0.x += p * v0.x; a0.y += p * v0.y; a0.z += p * v0.z; a0.w += p * v0.w;
            a1.x += p * v1.x; a1.y += p * v1.y; a1.z += p * v1.z; a1.w += p * v1.w;
        }
        __syncthreads();
    }
    int srow = q0 + q;
    if (srow < SEQ_) {
        float* o = g_att + (size_t)(b * SEQ_ + srow) * D_ + h * HD_ + dg * 8;
        a0.x = tf32_rna(a0.x); a0.y = tf32_rna(a0.y); a0.z = tf32_rna(a0.z); a0.w = tf32_rna(a0.w);
        a1.x = tf32_rna(a1.x); a1.y = tf32_rna(a1.y); a1.z = tf32_rna(a1.z); a1.w = tf32_rna(a1.w);
        *(float4*)o = a0;
        *(float4*)(o + 4) = a1;
    }
}

// ---------------- final head ----------------
__global__ void __launch_bounds__(256) head_kernel(
    const float* __restrict__ w, const float* __restrict__ bb,
    const float* __restrict__ proj, float* __restrict__ out)
{
    __shared__ float cls[D_];
    __shared__ float feats[E_];
    __shared__ float sm[16];
    int b = blockIdx.x;
    int tid = threadIdx.x;
    const float* xr = g_x + (size_t)(b * SEQ_) * D_;
    float v[3];
    #pragma unroll
    for (int i = 0; i < 3; i++) v[i] = xr[tid + i * 256];
    float sum = v[0] + v[1] + v[2];
    float sq = v[0] * v[0] + v[1] * v[1] + v[2] * v[2];
    block_sum2(sum, sq, sm);
    float mean = sum * (1.0f / D_);
    float var = sq * (1.0f / D_) - mean * mean;
    float r = rsqrtf(var + 1e-5f);
    #pragma unroll
    for (int i = 0; i < 3; i++) {
        int d = tid + i * 256;
        cls[d] = (v[i] - mean) * r * w[d] + bb[d];
    }
    __syncthreads();
    for (int e = tid; e < E_; e += 256) {
        float a = 0.f;
        for (int d = 0; d < D_; d++) a += cls[d] * proj[(size_t)d * E_ + e];
        feats[e] = a;
    }
    __syncthreads();
    float nrm = 0.f;
    for (int e = tid; e < E_; e += 256) nrm += feats[e] * feats[e];
    nrm = block_sum(nrm, sm);
    float rn = rsqrtf(nrm);
    for (int e = tid; e < E_; e += 256) out[(size_t)b * E_ + e] = feats[e] * rn;
}

// ---------------- host ----------------
extern "C" void kernel_launch(void* const* d_in, const int* in_sizes, int n_in,
                              void* d_out, int out_size)
{
    const float* image     = (const float*)d_in[0];
    const float* conv_w    = (const float*)d_in[1];
    const float* cls_emb   = (const float*)d_in[2];
    const float* pos_emb   = (const float*)d_in[3];
    const float* ln_pre_w  = (const float*)d_in[4];
    const float* ln_pre_b  = (const float*)d_in[5];
    const float* ln1_w     = (const float*)d_in[6];
    const float* ln1_b     = (const float*)d_in[7];
    const float* qkv_w     = (const float*)d_in[8];
    const float* qkv_b     = (const float*)d_in[9];
    const float* out_w     = (const float*)d_in[10];
    const float* out_b     = (const float*)d_in[11];
    const float* ln2_w     = (const float*)d_in[12];
    const float* ln2_b     = (const float*)d_in[13];
    const float* fc_w      = (const float*)d_in[14];
    const float* fc_b      = (const float*)d_in[15];
    const float* pr_w      = (const float*)d_in[16];
    const float* pr_b      = (const float*)d_in[17];
    const float* ln_post_w = (const float*)d_in[18];
    const float* ln_post_b = (const float*)d_in[19];
    const float* proj      = (const float*)d_in[20];
    float* out = (float*)d_out;
    (void)in_sizes; (void)n_in; (void)out_size;

    float *p_patch, *p_x, *p_ln, *p_qkv, *p_att, *p_ff;
    float *pw_qkv, *pw_out, *pw_fc, *pw_pr, *pw_conv;
    cudaGetSymbolAddress((void**)&p_patch, g_patch);
    cudaGetSymbolAddress((void**)&p_x,     g_x);
    cudaGetSymbolAddress((void**)&p_ln,    g_ln);
    cudaGetSymbolAddress((void**)&p_qkv,   g_qkv);
    cudaGetSymbolAddress((void**)&p_att,   g_att);
    cudaGetSymbolAddress((void**)&p_ff,    g_ff);
    cudaGetSymbolAddress((void**)&pw_qkv,  w_qkv);
    cudaGetSymbolAddress((void**)&pw_out,  w_out);
    cudaGetSymbolAddress((void**)&pw_fc,   w_fc);
    cudaGetSymbolAddress((void**)&pw_pr,   w_pr);
    cudaGetSymbolAddress((void**)&pw_conv, w_conv);

    cudaFuncSetAttribute(gemm_tc<0, false>, cudaFuncAttributeMaxDynamicSharedMemorySize, GSMEM_BYTES);
    cudaFuncSetAttribute(gemm_tc<1, false>, cudaFuncAttributeMaxDynamicSharedMemorySize, GSMEM_BYTES);
    cudaFuncSetAttribute(gemm_tc<2, true>,  cudaFuncAttributeMaxDynamicSharedMemorySize, GSMEM_BYTES);

    // tf32-round the weights into scratch copies
    auto rna = [&](const float* s, float* d, int n) {
        rna4_kernel<<<(n / 4 + 255) / 256, 256>>>((const float4*)s, (float4*)d, n / 4);
    };
    rna(qkv_w, pw_qkv, L_ * 3 * D_ * D_);
    rna(out_w, pw_out, L_ * D_ * D_);
    rna(fc_w,  pw_fc,  L_ * FF_ * D_);
    rna(pr_w,  pw_pr,  L_ * D_ * FF_);
    rna(conv_w, pw_conv, D_ * D_);

    const int MT = MP_ / 128;   // 50

    // patchify + conv-as-GEMM -> g_att
    patchify_kernel<<<(B_ * NP_ * D_ + 255) / 256, 256>>>(image);
    gemm_tc<0, false><<<dim3(MT, D_ / 256), 256, GSMEM_BYTES>>>(
        p_patch, pw_conv, nullptr, nullptr, p_att, D_, D_);
    embed_ln_kernel<<<NTOK, 256>>>(cls_emb, pos_emb, ln_pre_w, ln_pre_b);

    for (int l = 0; l < L_; l++) {
        ln_kernel<<<NTOK, 256>>>(p_x, p_ln, ln1_w + l * D_, ln1_b + l * D_);
        gemm_tc<0, false><<<dim3(MT, 3 * D_ / 256), 256, GSMEM_BYTES>>>(
            p_ln, pw_qkv + (size_t)l * 3 * D_ * D_, qkv_b + (size_t)l * 3 * D_,
            nullptr, p_qkv, 3 * D_, D_);
        attn2_kernel<<<dim3((SEQ_ + TQ_ - 1) / TQ_, B_ * H_), 256>>>();
        gemm_tc<1, false><<<dim3(MT, D_ / 256), 256, GSMEM_BYTES>>>(
            p_att, pw_out + (size_t)l * D_ * D_, out_b + (size_t)l * D_,
            p_x, p_x, D_, D_);
        ln_kernel<<<NTOK, 256>>>(p_x, p_ln, ln2_w + l * D_, ln2_b + l * D_);
        gemm_tc<2, true><<<dim3(MT, FF_ / 256), 256, GSMEM_BYTES>>>(
            p_ln, pw_fc + (size_t)l * FF_ * D_, fc_b + (size_t)l * FF_,
            nullptr, p_ff, FF_, D_);
        gemm_tc<1, false><<<dim3(MT, D_ / 256), 256, GSMEM_BYTES>>>(
            p_ff, pw_pr + (size_t)l * D_ * FF_, pr_b + (size_t)l * D_,
            p_x, p_x, D_, FF_);
    }
    head_kernel<<<B_, 256>>>(ln_post_w, ln_post_b, proj, out);
}

// round 5
// speedup vs baseline: 4.2382x; 1.4229x over previous
#include <cuda_runtime.h>
#include <cuda_fp16.h>
#include <math.h>
#include <stdint.h>

// ---------------- problem constants ----------------
#define D_    768
#define H_    12
#define HD_   64
#define FF_   3072
#define SEQ_  197
#define B_    32
#define NTOK  (B_ * SEQ_)     // 6304
#define MP_   6400            // padded token rows (50 * 128)
#define L_    12
#define E_    512
#define NP_   196
#define IMG_  224
#define P_    16

// ---------------- device scratch (no allocation allowed) ----------------
__device__ __half g_patch[MP_ * D_];
__device__ float  g_x[MP_ * D_];
__device__ __half g_ln[MP_ * D_];
__device__ float  g_qkv[MP_ * 3 * D_];    // also conv-gemm f32 output scratch
__device__ __half g_att[MP_ * D_];
__device__ __half g_ff[MP_ * FF_];
// fp16 weight copies
__device__ __half w_qkv[L_ * 3 * D_ * D_];
__device__ __half w_out[L_ * D_ * D_];
__device__ __half w_fc[L_ * FF_ * D_];
__device__ __half w_pr[L_ * D_ * FF_];
__device__ __half w_conv[D_ * D_];

// ---------------- helpers ----------------
__device__ __forceinline__ float gelu_exact(float v) {
    return 0.5f * v * (1.0f + erff(v * 0.70710678118654752f));
}
#define CP_ASYNC16(dst, src) \
    asm volatile("cp.async.cg.shared.global [%0], [%1], 16;\n" :: "r"(dst), "l"(src))
#define CP_COMMIT() asm volatile("cp.async.commit_group;\n" ::: "memory")
#define CP_WAIT1()  asm volatile("cp.async.wait_group 1;\n" ::: "memory")

__device__ __forceinline__ uint32_t smem_u32(const void* p) {
    uint32_t a;
    asm("{ .reg .u64 t; cvta.to.shared.u64 t, %1; cvt.u32.u64 %0, t; }" : "=r"(a) : "l"(p));
    return a;
}
__device__ __forceinline__ void mma_f16(float* c, const uint32_t* a, const uint32_t* b) {
    asm volatile(
        "mma.sync.aligned.m16n8k16.row.col.f32.f16.f16.f32 "
        "{%0,%1,%2,%3}, {%4,%5,%6,%7}, {%8,%9}, {%0,%1,%2,%3};"
        : "+f"(c[0]), "+f"(c[1]), "+f"(c[2]), "+f"(c[3])
        : "r"(a[0]), "r"(a[1]), "r"(a[2]), "r"(a[3]), "r"(b[0]), "r"(b[1]));
}
#define LDSM4(r, a) \
    asm volatile("ldmatrix.sync.aligned.m8n8.x4.shared.b16 {%0,%1,%2,%3}, [%4];" \
        : "=r"((r)[0]), "=r"((r)[1]), "=r"((r)[2]), "=r"((r)[3]) : "r"(a))

__device__ __forceinline__ uint32_t h2_u32(__half2 h) {
    return *reinterpret_cast<uint32_t*>(&h);
}

// ---------------- f32 -> f16 weight conversion ----------------
__global__ void f2h_kernel(const float4* __restrict__ s, __half* __restrict__ d, int n8) {
    int i = blockIdx.x * 256 + threadIdx.x;
    if (i >= n8) return;
    float4 a = s[i * 2], b = s[i * 2 + 1];
    uint4 u;
    u.x = h2_u32(__floats2half2_rn(a.x, a.y));
    u.y = h2_u32(__floats2half2_rn(a.z, a.w));
    u.z = h2_u32(__floats2half2_rn(b.x, b.y));
    u.w = h2_u32(__floats2half2_rn(b.z, b.w));
    *reinterpret_cast<uint4*>(d + (size_t)i * 8) = u;
}

// ---------------- fp16 tensor-core GEMM: C = A[M,K] * W[N,K]^T ----------------
// block tile 128x256x64, 8 warps (2x4), warp tile 64x64, m16n8k16 f16 MMA
// 3-stage cp.async pipeline, XOR-swizzled smem, ldmatrix fragment loads
// MODE 0: C = acc + bias ; MODE 1: C = res + acc + bias ; MODE 2: C = gelu(acc + bias)
// HOUT: write __half (else float)
#define STAGE_BYTES 49152u          // A tile 16KB + B tile 32KB (half, BK=64)
#define GSMEM_BYTES (3 * 49152)

template <int MODE, bool HOUT>
__global__ void __launch_bounds__(256) gemm_tc(
    const __half* __restrict__ A, const __half* __restrict__ W,
    const float* __restrict__ bias, const float* __restrict__ res,
    void* __restrict__ Cv, int N, int K)
{
    extern __shared__ float smem[];
    uint32_t sbase = smem_u32(smem);
    int tid = threadIdx.x;
    int wid = tid >> 5, lane = tid & 31;
    int g = lane >> 2, t = lane & 3;
    int warpM = wid & 1, warpN = wid >> 1;       // 2 x 4 warp grid

    int row0 = blockIdx.x * 128;
    int col0 = blockIdx.y * 256;
    const __half* Abase = A + (size_t)row0 * K;
    const __half* Wbase = W + (size_t)col0 * K;

    auto load_stage = [&](int s, int k0) {
        uint32_t ab = sbase + (uint32_t)s * STAGE_BYTES;
        uint32_t bb = ab + 16384u;
        #pragma unroll
        for (int i = 0; i < 4; i++) {
            int idx = tid + i * 256;
            int r = idx >> 3, c = idx & 7;          // 8-halve (16B) chunks
            uint32_t d = ab + (uint32_t)(r * 128 + ((c ^ (r & 7)) * 16));
            CP_ASYNC16(d, Abase + (size_t)r * K + k0 + c * 8);
        }
        #pragma unroll
        for (int i = 0; i < 8; i++) {
            int idx = tid + i * 256;
            int r = idx >> 3, c = idx & 7;
            uint32_t d = bb + (uint32_t)(r * 128 + ((c ^ (r & 7)) * 16));
            CP_ASYNC16(d, Wbase + (size_t)r * K + k0 + c * 8);
        }
        CP_COMMIT();
    };

    float acc[4][8][4];
    #pragma unroll
    for (int i = 0; i < 4; i++)
        #pragma unroll
        for (int j = 0; j < 8; j++)
            #pragma unroll
            for (int r = 0; r < 4; r++) acc[i][j][r] = 0.f;

    // ldmatrix per-lane address components (chunks are 16B = 8 halves)
    int ar = lane & 15;                        // A fragment row within 16
    int asel = lane >> 4;                      // A k-half select
    int brr = (lane & 7) + ((lane >> 4) << 3); // B fragment row within 16
    int bsel = (lane >> 3) & 1;                // B k-half select
    uint32_t aRow[4], bRow[4], aChunk[4], bChunk[4];
    #pragma unroll
    for (int mt = 0; mt < 4; mt++)
        aRow[mt] = (uint32_t)((warpM * 64 + mt * 16 + ar) * 128);
    #pragma unroll
    for (int nt2 = 0; nt2 < 4; nt2++)
        bRow[nt2] = (uint32_t)((warpN * 64 + nt2 * 16 + brr) * 128);
    #pragma unroll
    for (int kt = 0; kt < 4; kt++) {
        aChunk[kt] = (uint32_t)((((kt * 2 + asel) ^ (lane & 7)) * 16));
        bChunk[kt] = (uint32_t)((((kt * 2 + bsel) ^ (lane & 7)) * 16));
    }

    int nIter = K >> 6;                        // BK = 64
    load_stage(0, 0);
    load_stage(1, 64);

    for (int it = 0; it < nIter; it++) {
        CP_WAIT1();
        __syncthreads();
        if (it + 2 < nIter) load_stage((it + 2) % 3, (it + 2) * 64);
        else CP_COMMIT();

        uint32_t ab = sbase + (uint32_t)(it % 3) * STAGE_BYTES;
        uint32_t bb = ab + 16384u;
        #pragma unroll
        for (int kt = 0; kt < 4; kt++) {       // 4 x k16
            uint32_t af[4][4], bf[4][4];
            #pragma unroll
            for (int mt = 0; mt < 4; mt++)
                LDSM4(af[mt], ab + aRow[mt] + aChunk[kt]);
            #pragma unroll
            for (int nt2 = 0; nt2 < 4; nt2++)
                LDSM4(bf[nt2], bb + bRow[nt2] + bChunk[kt]);
            #pragma unroll
            for (int mt = 0; mt < 4; mt++)
                #pragma unroll
                for (int nt2 = 0; nt2 < 4; nt2++) {
                    mma_f16(acc[mt][nt2 * 2],     af[mt], &bf[nt2][0]);
                    mma_f16(acc[mt][nt2 * 2 + 1], af[mt], &bf[nt2][2]);
                }
        }
    }

    // ---------------- epilogue ----------------
    #pragma unroll
    for (int nt = 0; nt < 8; nt++) {
        int col = col0 + warpN * 64 + nt * 8 + 2 * t;
        float2 bv = make_float2(0.f, 0.f);
        if (bias) bv = *(const float2*)(bias + col);
        #pragma unroll
        for (int mt = 0; mt < 4; mt++) {
            int row = row0 + warpM * 64 + mt * 16 + g;
            #pragma unroll
            for (int half_ = 0; half_ < 2; half_++) {
                int r = row + half_ * 8;
                float2 v;
                v.x = acc[mt][nt][half_ * 2 + 0] + bv.x;
                v.y = acc[mt][nt][half_ * 2 + 1] + bv.y;
                if (MODE == 1) {
                    float2 rv = *(const float2*)(res + (size_t)r * N + col);
                    v.x += rv.x; v.y += rv.y;
                }
                if (MODE == 2) { v.x = gelu_exact(v.x); v.y = gelu_exact(v.y); }
                if (HOUT) {
                    *reinterpret_cast<__half2*>((__half*)Cv + (size_t)r * N + col) =
                        __floats2half2_rn(v.x, v.y);
                } else {
                    *(float2*)((float*)Cv + (size_t)r * N + col) = v;
                }
            }
        }
    }
}

// ---------------- patchify (im2col gather -> fp16) ----------------
__global__ void patchify_kernel(const float* __restrict__ img) {
    int idx = blockIdx.x * 256 + threadIdx.x;
    if (idx >= B_ * NP_ * D_) return;
    int k = idx % D_;
    int bp = idx / D_;
    int p = bp % NP_;
    int b = bp / NP_;
    int c = k >> 8;
    int rem = k & 255;
    int dy = rem >> 4, dx = rem & 15;
    int y = (p / 14) * P_ + dy;
    int x = (p % 14) * P_ + dx;
    g_patch[idx] = __float2half(img[(((size_t)b * 3 + c) * IMG_ + y) * IMG_ + x]);
}

// ---------------- reductions ----------------
__device__ __forceinline__ void block_sum2(float& a, float& b, float* sm) {
    #pragma unroll
    for (int o = 16; o; o >>= 1) {
        a += __shfl_xor_sync(0xffffffffu, a, o);
        b += __shfl_xor_sync(0xffffffffu, b, o);
    }
    int warp = threadIdx.x >> 5, lane = threadIdx.x & 31;
    int nw = blockDim.x >> 5;
    if (lane == 0) { sm[warp] = a; sm[warp + 8] = b; }
    __syncthreads();
    if (threadIdx.x == 0) {
        float sa = 0.f, sb = 0.f;
        for (int i = 0; i < nw; i++) { sa += sm[i]; sb += sm[i + 8]; }
        sm[0] = sa; sm[8] = sb;
    }
    __syncthreads();
    a = sm[0]; b = sm[8];
    __syncthreads();
}
__device__ __forceinline__ float block_sum(float v, float* sm) {
    #pragma unroll
    for (int o = 16; o; o >>= 1) v += __shfl_xor_sync(0xffffffffu, v, o);
    int warp = threadIdx.x >> 5, lane = threadIdx.x & 31;
    int nw = blockDim.x >> 5;
    if (lane == 0) sm[warp] = v;
    __syncthreads();
    if (threadIdx.x == 0) {
        float s = 0.f;
        for (int i = 0; i < nw; i++) s += sm[i];
        sm[0] = s;
    }
    __syncthreads();
    v = sm[0];
    __syncthreads();
    return v;
}

// ---------------- embed + ln_pre (conv output read from g_qkv f32) ----------
__global__ void __launch_bounds__(256) embed_ln_kernel(
    const float* __restrict__ cls_emb, const float* __restrict__ pos_emb,
    const float* __restrict__ w, const float* __restrict__ bb)
{
    __shared__ float sm[16];
    int row = blockIdx.x;
    int b = row / SEQ_, s = row % SEQ_;
    int tid = threadIdx.x;
    float v[3];
    #pragma unroll
    for (int i = 0; i < 3; i++) {
        int d = tid + i * 256;
        float base = (s == 0) ? cls_emb[d]
                              : g_qkv[((size_t)(b * NP_ + (s - 1))) * D_ + d];
        v[i] = base + pos_emb[(size_t)s * D_ + d];
    }
    float sum = v[0] + v[1] + v[2];
    float sq = v[0] * v[0] + v[1] * v[1] + v[2] * v[2];
    block_sum2(sum, sq, sm);
    float mean = sum * (1.0f / D_);
    float var = sq * (1.0f / D_) - mean * mean;
    float r = rsqrtf(var + 1e-5f);
    #pragma unroll
    for (int i = 0; i < 3; i++) {
        int d = tid + i * 256;
        g_x[(size_t)row * D_ + d] = (v[i] - mean) * r * w[d] + bb[d];
    }
}

// ---------------- layernorm (f32 in -> fp16 out, feeds GEMM A) ----------------
__global__ void __launch_bounds__(256) ln_kernel(
    const float* __restrict__ x, __half* __restrict__ y,
    const float* __restrict__ w, const float* __restrict__ bb)
{
    __shared__ float sm[16];
    int row = blockIdx.x;
    int tid = threadIdx.x;
    const float* xr = x + (size_t)row * D_;
    float v[3];
    #pragma unroll
    for (int i = 0; i < 3; i++) v[i] = xr[tid + i * 256];
    float sum = v[0] + v[1] + v[2];
    float sq = v[0] * v[0] + v[1] * v[1] + v[2] * v[2];
    block_sum2(sum, sq, sm);
    float mean = sum * (1.0f / D_);
    float var = sq * (1.0f / D_) - mean * mean;
    float r = rsqrtf(var + 1e-5f);
    __half* yr = y + (size_t)row * D_;
    #pragma unroll
    for (int i = 0; i < 3; i++) {
        int d = tid + i * 256;
        yr[d] = __float2half((v[i] - mean) * r * w[d] + bb[d]);
    }
}

// ---------------- attention: 32 queries per block, K/V tiled in smem --------
#define TQ_ 32
__global__ void __launch_bounds__(256) attn2_kernel() {
    __shared__ __align__(16) float Ks[64][68];
    __shared__ __align__(16) float sc[TQ_][200];
    int q0 = blockIdx.x * TQ_;
    int bh = blockIdx.y;
    int b = bh / H_, h = bh % H_;
    int tid = threadIdx.x;
    size_t base = (size_t)(b * SEQ_) * (3 * D_) + (size_t)h * HD_;

    // stage Q (scaled), then keep in registers
    float* Qtmp = &sc[0][0];
    for (int i = tid; i < TQ_ * 16; i += 256) {
        int r = i >> 4, j = i & 15;
        int srow = q0 + r;
        float4 v = make_float4(0.f, 0.f, 0.f, 0.f);
        if (srow < SEQ_)
            v = *(const float4*)(g_qkv + base + (size_t)srow * (3 * D_) + j * 4);
        v.x *= 0.125f; v.y *= 0.125f; v.z *= 0.125f; v.w *= 0.125f;
        *(float4*)(Qtmp + r * 64 + j * 4) = v;
    }
    __syncthreads();
    int q = tid >> 3, toff = tid & 7;
    float4 rq[16];
    #pragma unroll
    for (int j = 0; j < 16; j++) rq[j] = *(const float4*)(Qtmp + q * 64 + j * 4);
    __syncthreads();

    // scores
    for (int t0 = 0; t0 < SEQ_; t0 += 64) {
        int len = min(64, SEQ_ - t0);
        for (int i = tid; i < len * 16; i += 256) {
            int r = i >> 4, j = i & 15;
            float4 kv = *(const float4*)(g_qkv + base + D_ + (size_t)(t0 + r) * (3 * D_) + j * 4);
            *(float4*)(&Ks[r][j * 4]) = kv;
        }
        __syncthreads();
        for (int tt = toff; tt < len; tt += 8) {
            float a = 0.f;
            #pragma unroll
            for (int j = 0; j < 16; j++) {
                float4 kv = *(const float4*)(&Ks[tt][j * 4]);
                a += rq[j].x * kv.x + rq[j].y * kv.y + rq[j].z * kv.z + rq[j].w * kv.w;
            }
            sc[q][t0 + tt] = a;
        }
        __syncthreads();
    }

    // softmax: warp w handles 4 rows
    {
        int lane = tid & 31, w = tid >> 5;
        for (int r = w * 4; r < w * 4 + 4; r++) {
            float mx = -1e30f;
            for (int tt = lane; tt < SEQ_; tt += 32) mx = fmaxf(mx, sc[r][tt]);
            #pragma unroll
            for (int o = 16; o; o >>= 1) mx = fmaxf(mx, __shfl_xor_sync(0xffffffffu, mx, o));
            float s = 0.f;
            for (int tt = lane; tt < SEQ_; tt += 32) {
                float e = expf(sc[r][tt] - mx);
                sc[r][tt] = e;
                s += e;
            }
            #pragma unroll
            for (int o = 16; o; o >>= 1) s += __shfl_xor_sync(0xffffffffu, s, o);
            float inv = 1.0f / s;
            for (int tt = lane; tt < SEQ_; tt += 32) sc[r][tt] *= inv;
        }
    }
    __syncthreads();

    // o = p @ V  -> fp16 output
    int dg = tid & 7;
    float4 a0 = make_float4(0.f, 0.f, 0.f, 0.f);
    float4 a1 = make_float4(0.f, 0.f, 0.f, 0.f);
    for (int t0 = 0; t0 < SEQ_; t0 += 64) {
        int len = min(64, SEQ_ - t0);
        for (int i = tid; i < len * 16; i += 256) {
            int r = i >> 4, j = i & 15;
            float4 vv = *(const float4*)(g_qkv + base + 2 * D_ + (size_t)(t0 + r) * (3 * D_) + j * 4);
            *(float4*)(&Ks[r][j * 4]) = vv;
        }
        __syncthreads();
        for (int tt = 0; tt < len; tt++) {
            float p = sc[q][t0 + tt];
            float4 v0 = *(const float4*)(&Ks[tt][dg * 8]);
            float4 v1 = *(const float4*)(&Ks[tt][dg * 8 + 4]);
            a0.x += p * v0.x; a0.y += p * v0.y; a0.z += p * v0.z; a0.w += p * v0.w;
            a1.x += p * v1.x; a1.y += p * v1.y; a1.z += p * v1.z; a1.w += p * v1.w;
        }
        __syncthreads();
    }
    int srow = q0 + q;
    if (srow < SEQ_) {
        __half* o = g_att + (size_t)(b * SEQ_ + srow) * D_ + h * HD_ + dg * 8;
        uint4 u;
        u.x = h2_u32(__floats2half2_rn(a0.x, a0.y));
        u.y = h2_u32(__floats2half2_rn(a0.z, a0.w));
        u.z = h2_u32(__floats2half2_rn(a1.x, a1.y));
        u.w = h2_u32(__floats2half2_rn(a1.z, a1.w));
        *reinterpret_cast<uint4*>(o) = u;
    }
}

// ---------------- final head ----------------
__global__ void __launch_bounds__(256) head_kernel(
    const float* __restrict__ w, const float* __restrict__ bb,
    const float* __restrict__ proj, float* __restrict__ out)
{
    __shared__ float cls[D_];
    __shared__ float feats[E_];
    __shared__ float sm[16];
    int b = blockIdx.x;
    int tid = threadIdx.x;
    const float* xr = g_x + (size_t)(b * SEQ_) * D_;
    float v[3];
    #pragma unroll
    for (int i = 0; i < 3; i++) v[i] = xr[tid + i * 256];
    float sum = v[0] + v[1] + v[2];
    float sq = v[0] * v[0] + v[1] * v[1] + v[2] * v[2];
    block_sum2(sum, sq, sm);
    float mean = sum * (1.0f / D_);
    float var = sq * (1.0f / D_) - mean * mean;
    float r = rsqrtf(var + 1e-5f);
    #pragma unroll
    for (int i = 0; i < 3; i++) {
        int d = tid + i * 256;
        cls[d] = (v[i] - mean) * r * w[d] + bb[d];
    }
    __syncthreads();
    for (int e = tid; e < E_; e += 256) {
        float a = 0.f;
        for (int d = 0; d < D_; d++) a += cls[d] * proj[(size_t)d * E_ + e];
        feats[e] = a;
    }
    __syncthreads();
    float nrm = 0.f;
    for (int e = tid; e < E_; e += 256) nrm += feats[e] * feats[e];
    nrm = block_sum(nrm, sm);
    float rn = rsqrtf(nrm);
    for (int e = tid; e < E_; e += 256) out[(size_t)b * E_ + e] = feats[e] * rn;
}

// ---------------- host ----------------
extern "C" void kernel_launch(void* const* d_in, const int* in_sizes, int n_in,
                              void* d_out, int out_size)
{
    const float* image     = (const float*)d_in[0];
    const float* conv_w    = (const float*)d_in[1];
    const float* cls_emb   = (const float*)d_in[2];
    const float* pos_emb   = (const float*)d_in[3];
    const float* ln_pre_w  = (const float*)d_in[4];
    const float* ln_pre_b  = (const float*)d_in[5];
    const float* ln1_w     = (const float*)d_in[6];
    const float* ln1_b     = (const float*)d_in[7];
    const float* qkv_w     = (const float*)d_in[8];
    const float* qkv_b     = (const float*)d_in[9];
    const float* out_w     = (const float*)d_in[10];
    const float* out_b     = (const float*)d_in[11];
    const float* ln2_w     = (const float*)d_in[12];
    const float* ln2_b     = (const float*)d_in[13];
    const float* fc_w      = (const float*)d_in[14];
    const float* fc_b      = (const float*)d_in[15];
    const float* pr_w      = (const float*)d_in[16];
    const float* pr_b      = (const float*)d_in[17];
    const float* ln_post_w = (const float*)d_in[18];
    const float* ln_post_b = (const float*)d_in[19];
    const float* proj      = (const float*)d_in[20];
    float* out = (float*)d_out;
    (void)in_sizes; (void)n_in; (void)out_size;

    __half *p_patch, *p_ln, *p_att, *p_ff;
    float  *p_x, *p_qkv;
    __half *pw_qkv, *pw_out, *pw_fc, *pw_pr, *pw_conv;
    cudaGetSymbolAddress((void**)&p_patch, g_patch);
    cudaGetSymbolAddress((void**)&p_x,     g_x);
    cudaGetSymbolAddress((void**)&p_ln,    g_ln);
    cudaGetSymbolAddress((void**)&p_qkv,   g_qkv);
    cudaGetSymbolAddress((void**)&p_att,   g_att);
    cudaGetSymbolAddress((void**)&p_ff,    g_ff);
    cudaGetSymbolAddress((void**)&pw_qkv,  w_qkv);
    cudaGetSymbolAddress((void**)&pw_out,  w_out);
    cudaGetSymbolAddress((void**)&pw_fc,   w_fc);
    cudaGetSymbolAddress((void**)&pw_pr,   w_pr);
    cudaGetSymbolAddress((void**)&pw_conv, w_conv);

    cudaFuncSetAttribute(gemm_tc<0, false>, cudaFuncAttributeMaxDynamicSharedMemorySize, GSMEM_BYTES);
    cudaFuncSetAttribute(gemm_tc<1, false>, cudaFuncAttributeMaxDynamicSharedMemorySize, GSMEM_BYTES);
    cudaFuncSetAttribute(gemm_tc<2, true>,  cudaFuncAttributeMaxDynamicSharedMemorySize, GSMEM_BYTES);

    // fp16 weight copies
    auto cvt = [&](const float* s, __half* d, int n) {
        f2h_kernel<<<(n / 8 + 255) / 256, 256>>>((const float4*)s, d, n / 8);
    };
    cvt(qkv_w, pw_qkv, L_ * 3 * D_ * D_);
    cvt(out_w, pw_out, L_ * D_ * D_);
    cvt(fc_w,  pw_fc,  L_ * FF_ * D_);
    cvt(pr_w,  pw_pr,  L_ * D_ * FF_);
    cvt(conv_w, pw_conv, D_ * D_);

    const int MT = MP_ / 128;   // 50

    // patchify + conv-as-GEMM -> g_qkv (f32 scratch)
    patchify_kernel<<<(B_ * NP_ * D_ + 255) / 256, 256>>>(image);
    gemm_tc<0, false><<<dim3(MT, D_ / 256), 256, GSMEM_BYTES>>>(
        p_patch, pw_conv, nullptr, nullptr, p_qkv, D_, D_);
    embed_ln_kernel<<<NTOK, 256>>>(cls_emb, pos_emb, ln_pre_w, ln_pre_b);

    for (int l = 0; l < L_; l++) {
        ln_kernel<<<NTOK, 256>>>(p_x, p_ln, ln1_w + l * D_, ln1_b + l * D_);
        gemm_tc<0, false><<<dim3(MT, 3 * D_ / 256), 256, GSMEM_BYTES>>>(
            p_ln, pw_qkv + (size_t)l * 3 * D_ * D_, qkv_b + (size_t)l * 3 * D_,
            nullptr, p_qkv, 3 * D_, D_);
        attn2_kernel<<<dim3((SEQ_ + TQ_ - 1) / TQ_, B_ * H_), 256>>>();
        gemm_tc<1, false><<<dim3(MT, D_ / 256), 256, GSMEM_BYTES>>>(
            p_att, pw_out + (size_t)l * D_ * D_, out_b + (size_t)l * D_,
            p_x, p_x, D_, D_);
        ln_kernel<<<NTOK, 256>>>(p_x, p_ln, ln2_w + l * D_, ln2_b + l * D_);
        gemm_tc<2, true><<<dim3(MT, FF_ / 256), 256, GSMEM_BYTES>>>(
            p_ln, pw_fc + (size_t)l * FF_ * D_, fc_b + (size_t)l * FF_,
            nullptr, p_ff, FF_, D_);
        gemm_tc<1, false><<<dim3(MT, D_ / 256), 256, GSMEM_BYTES>>>(
            p_ff, pw_pr + (size_t)l * D_ * FF_, pr_b + (size_t)l * D_,
            p_x, p_x, D_, FF_);
    }
    head_kernel<<<B_, 256>>>(ln_post_w, ln_post_b, proj, out);
}

// round 7
// speedup vs baseline: 4.7920x; 1.1307x over previous
#include <cuda_runtime.h>
#include <cuda_fp16.h>
#include <math.h>
#include <stdint.h>

// ---------------- problem constants ----------------
#define D_    768
#define H_    12
#define HD_   64
#define FF_   3072
#define SEQ_  197
#define B_    32
#define NTOK  (B_ * SEQ_)     // 6304
#define MP_   6400            // padded token rows (50 * 128)
#define L_    12
#define E_    512
#define NP_   196
#define IMG_  224
#define P_    16

// ---------------- device scratch (no allocation allowed) ----------------
__device__ __half g_patch[MP_ * D_];
__device__ float  g_x[MP_ * D_];
__device__ __half g_ln[MP_ * D_];
__device__ float  g_qkv[MP_ * 3 * D_];    // also conv-gemm f32 output scratch
__device__ __half g_att[MP_ * D_];
__device__ __half g_ff[MP_ * FF_];
// fp16 weight copies
__device__ __half w_qkv[L_ * 3 * D_ * D_];
__device__ __half w_out[L_ * D_ * D_];
__device__ __half w_fc[L_ * FF_ * D_];
__device__ __half w_pr[L_ * D_ * FF_];
__device__ __half w_conv[D_ * D_];

// ---------------- helpers ----------------
__device__ __forceinline__ float gelu_exact(float v) {
    return 0.5f * v * (1.0f + erff(v * 0.70710678118654752f));
}
#define CP_ASYNC16(dst, src) \
    asm volatile("cp.async.cg.shared.global [%0], [%1], 16;\n" :: "r"(dst), "l"(src))
#define CP_COMMIT() asm volatile("cp.async.commit_group;\n" ::: "memory")
#define CP_WAIT1()  asm volatile("cp.async.wait_group 1;\n" ::: "memory")

__device__ __forceinline__ uint32_t smem_u32(const void* p) {
    uint32_t a;
    asm("{ .reg .u64 t; cvta.to.shared.u64 t, %1; cvt.u32.u64 %0, t; }" : "=r"(a) : "l"(p));
    return a;
}
__device__ __forceinline__ void mma_f16(float* c, const uint32_t* a, const uint32_t* b) {
    asm volatile(
        "mma.sync.aligned.m16n8k16.row.col.f32.f16.f16.f32 "
        "{%0,%1,%2,%3}, {%4,%5,%6,%7}, {%8,%9}, {%0,%1,%2,%3};"
        : "+f"(c[0]), "+f"(c[1]), "+f"(c[2]), "+f"(c[3])
        : "r"(a[0]), "r"(a[1]), "r"(a[2]), "r"(a[3]), "r"(b[0]), "r"(b[1]));
}
#define LDSM4(r, a) \
    asm volatile("ldmatrix.sync.aligned.m8n8.x4.shared.b16 {%0,%1,%2,%3}, [%4];" \
        : "=r"((r)[0]), "=r"((r)[1]), "=r"((r)[2]), "=r"((r)[3]) : "r"(a))

__device__ __forceinline__ uint32_t h2_u32(__half2 h) {
    return *reinterpret_cast<uint32_t*>(&h);
}

// ---------------- f32 -> f16 weight conversion ----------------
__global__ void f2h_kernel(const float4* __restrict__ s, __half* __restrict__ d, int n8) {
    int i = blockIdx.x * 256 + threadIdx.x;
    if (i >= n8) return;
    float4 a = s[i * 2], b = s[i * 2 + 1];
    uint4 u;
    u.x = h2_u32(__floats2half2_rn(a.x, a.y));
    u.y = h2_u32(__floats2half2_rn(a.z, a.w));
    u.z = h2_u32(__floats2half2_rn(b.x, b.y));
    u.w = h2_u32(__floats2half2_rn(b.z, b.w));
    *reinterpret_cast<uint4*>(d + (size_t)i * 8) = u;
}

// ---------------- fp16 tensor-core GEMM: C = A[M,K] * W[N,K]^T ----------------
// block tile 128x128x64, 8 warps (4x2), warp tile 32x64, m16n8k16 f16 MMA
// 3-stage cp.async pipeline (32KB/stage -> 2 CTAs per SM), XOR-swizzled smem
// MODE 0: C = acc + bias ; MODE 1: C = res + acc + bias ; MODE 2: C = gelu(acc + bias)
// HOUT: write __half (else float)
#define STAGE_BYTES 32768u          // A tile 16KB + B tile 16KB (half, BK=64)
#define GSMEM_BYTES (3 * 32768)

template <int MODE, bool HOUT>
__global__ void __launch_bounds__(256, 2) gemm_tc(
    const __half* __restrict__ A, const __half* __restrict__ W,
    const float* __restrict__ bias, const float* __restrict__ res,
    void* __restrict__ Cv, int N, int K)
{
    extern __shared__ float smem[];
    uint32_t sbase = smem_u32(smem);
    int tid = threadIdx.x;
    int wid = tid >> 5, lane = tid & 31;
    int g = lane >> 2, t = lane & 3;
    int warpM = wid & 3, warpN = wid >> 2;       // 4 x 2 warp grid

    int row0 = blockIdx.x * 128;
    int col0 = blockIdx.y * 128;
    const __half* Abase = A + (size_t)row0 * K;
    const __half* Wbase = W + (size_t)col0 * K;

    auto load_stage = [&](int s, int k0) {
        uint32_t ab = sbase + (uint32_t)s * STAGE_BYTES;
        uint32_t bb = ab + 16384u;
        #pragma unroll
        for (int i = 0; i < 4; i++) {
            int idx = tid + i * 256;
            int r = idx >> 3, c = idx & 7;          // 8-halve (16B) chunks
            uint32_t d = ab + (uint32_t)(r * 128 + ((c ^ (r & 7)) * 16));
            CP_ASYNC16(d, Abase + (size_t)r * K + k0 + c * 8);
        }
        #pragma unroll
        for (int i = 0; i < 4; i++) {
            int idx = tid + i * 256;
            int r = idx >> 3, c = idx & 7;
            uint32_t d = bb + (uint32_t)(r * 128 + ((c ^ (r & 7)) * 16));
            CP_ASYNC16(d, Wbase + (size_t)r * K + k0 + c * 8);
        }
        CP_COMMIT();
    };

    float acc[2][8][4];
    #pragma unroll
    for (int i = 0; i < 2; i++)
        #pragma unroll
        for (int j = 0; j < 8; j++)
            #pragma unroll
            for (int r = 0; r < 4; r++) acc[i][j][r] = 0.f;

    // ldmatrix per-lane address components (chunks are 16B = 8 halves)
    int ar = lane & 15;                        // A fragment row within 16
    int asel = lane >> 4;                      // A k-half select
    int brr = (lane & 7) + ((lane >> 4) << 3); // B fragment row within 16
    int bsel = (lane >> 3) & 1;                // B k-half select
    uint32_t aRow[2], bRow[4], aChunk[4], bChunk[4];
    #pragma unroll
    for (int mt = 0; mt < 2; mt++)
        aRow[mt] = (uint32_t)((warpM * 32 + mt * 16 + ar) * 128);
    #pragma unroll
    for (int nt2 = 0; nt2 < 4; nt2++)
        bRow[nt2] = (uint32_t)((warpN * 64 + nt2 * 16 + brr) * 128);
    #pragma unroll
    for (int kt = 0; kt < 4; kt++) {
        aChunk[kt] = (uint32_t)((((kt * 2 + asel) ^ (lane & 7)) * 16));
        bChunk[kt] = (uint32_t)((((kt * 2 + bsel) ^ (lane & 7)) * 16));
    }

    int nIter = K >> 6;                        // BK = 64
    load_stage(0, 0);
    load_stage(1, 64);

    for (int it = 0; it < nIter; it++) {
        CP_WAIT1();
        __syncthreads();
        if (it + 2 < nIter) load_stage((it + 2) % 3, (it + 2) * 64);
        else CP_COMMIT();

        uint32_t ab = sbase + (uint32_t)(it % 3) * STAGE_BYTES;
        uint32_t bb = ab + 16384u;
        #pragma unroll
        for (int kt = 0; kt < 4; kt++) {       // 4 x k16
            uint32_t af[2][4], bf[4][4];
            #pragma unroll
            for (int mt = 0; mt < 2; mt++)
                LDSM4(af[mt], ab + aRow[mt] + aChunk[kt]);
            #pragma unroll
            for (int nt2 = 0; nt2 < 4; nt2++)
                LDSM4(bf[nt2], bb + bRow[nt2] + bChunk[kt]);
            #pragma unroll
            for (int mt = 0; mt < 2; mt++)
                #pragma unroll
                for (int nt2 = 0; nt2 < 4; nt2++) {
                    mma_f16(acc[mt][nt2 * 2],     af[mt], &bf[nt2][0]);
                    mma_f16(acc[mt][nt2 * 2 + 1], af[mt], &bf[nt2][2]);
                }
        }
    }

    // ---------------- epilogue ----------------
    #pragma unroll
    for (int nt = 0; nt < 8; nt++) {
        int col = col0 + warpN * 64 + nt * 8 + 2 * t;
        float2 bv = make_float2(0.f, 0.f);
        if (bias) bv = *(const float2*)(bias + col);
        #pragma unroll
        for (int mt = 0; mt < 2; mt++) {
            int row = row0 + warpM * 32 + mt * 16 + g;
            #pragma unroll
            for (int half_ = 0; half_ < 2; half_++) {
                int r = row + half_ * 8;
                float2 v;
                v.x = acc[mt][nt][half_ * 2 + 0] + bv.x;
                v.y = acc[mt][nt][half_ * 2 + 1] + bv.y;
                if (MODE == 1) {
                    float2 rv = *(const float2*)(res + (size_t)r * N + col);
                    v.x += rv.x; v.y += rv.y;
                }
                if (MODE == 2) { v.x = gelu_exact(v.x); v.y = gelu_exact(v.y); }
                if (HOUT) {
                    *reinterpret_cast<__half2*>((__half*)Cv + (size_t)r * N + col) =
                        __floats2half2_rn(v.x, v.y);
                } else {
                    *(float2*)((float*)Cv + (size_t)r * N + col) = v;
                }
            }
        }
    }
}

// ---------------- patchify (im2col gather -> fp16) ----------------
__global__ void patchify_kernel(const float* __restrict__ img) {
    int idx = blockIdx.x * 256 + threadIdx.x;
    if (idx >= B_ * NP_ * D_) return;
    int k = idx % D_;
    int bp = idx / D_;
    int p = bp % NP_;
    int b = bp / NP_;
    int c = k >> 8;
    int rem = k & 255;
    int dy = rem >> 4, dx = rem & 15;
    int y = (p / 14) * P_ + dy;
    int x = (p % 14) * P_ + dx;
    g_patch[idx] = __float2half(img[(((size_t)b * 3 + c) * IMG_ + y) * IMG_ + x]);
}

// ---------------- reductions ----------------
__device__ __forceinline__ void block_sum2(float& a, float& b, float* sm) {
    #pragma unroll
    for (int o = 16; o; o >>= 1) {
        a += __shfl_xor_sync(0xffffffffu, a, o);
        b += __shfl_xor_sync(0xffffffffu, b, o);
    }
    int warp = threadIdx.x >> 5, lane = threadIdx.x & 31;
    int nw = blockDim.x >> 5;
    if (lane == 0) { sm[warp] = a; sm[warp + 8] = b; }
    __syncthreads();
    if (threadIdx.x == 0) {
        float sa = 0.f, sb = 0.f;
        for (int i = 0; i < nw; i++) { sa += sm[i]; sb += sm[i + 8]; }
        sm[0] = sa; sm[8] = sb;
    }
    __syncthreads();
    a = sm[0]; b = sm[8];
    __syncthreads();
}
__device__ __forceinline__ float block_sum(float v, float* sm) {
    #pragma unroll
    for (int o = 16; o; o >>= 1) v += __shfl_xor_sync(0xffffffffu, v, o);
    int warp = threadIdx.x >> 5, lane = threadIdx.x & 31;
    int nw = blockDim.x >> 5;
    if (lane == 0) sm[warp] = v;
    __syncthreads();
    if (threadIdx.x == 0) {
        float s = 0.f;
        for (int i = 0; i < nw; i++) s += sm[i];
        sm[0] = s;
    }
    __syncthreads();
    v = sm[0];
    __syncthreads();
    return v;
}

// ---------------- embed + ln_pre (conv output read from g_qkv f32) ----------
__global__ void __launch_bounds__(256) embed_ln_kernel(
    const float* __restrict__ cls_emb, const float* __restrict__ pos_emb,
    const float* __restrict__ w, const float* __restrict__ bb)
{
    __shared__ float sm[16];
    int row = blockIdx.x;
    int b = row / SEQ_, s = row % SEQ_;
    int tid = threadIdx.x;
    float v[3];
    #pragma unroll
    for (int i = 0; i < 3; i++) {
        int d = tid + i * 256;
        float base = (s == 0) ? cls_emb[d]
                              : g_qkv[((size_t)(b * NP_ + (s - 1))) * D_ + d];
        v[i] = base + pos_emb[(size_t)s * D_ + d];
    }
    float sum = v[0] + v[1] + v[2];
    float sq = v[0] * v[0] + v[1] * v[1] + v[2] * v[2];
    block_sum2(sum, sq, sm);
    float mean = sum * (1.0f / D_);
    float var = sq * (1.0f / D_) - mean * mean;
    float r = rsqrtf(var + 1e-5f);
    #pragma unroll
    for (int i = 0; i < 3; i++) {
        int d = tid + i * 256;
        g_x[(size_t)row * D_ + d] = (v[i] - mean) * r * w[d] + bb[d];
    }
}

// ---------------- layernorm (f32 in -> fp16 out, feeds GEMM A) ----------------
__global__ void __launch_bounds__(256) ln_kernel(
    const float* __restrict__ x, __half* __restrict__ y,
    const float* __restrict__ w, const float* __restrict__ bb)
{
    __shared__ float sm[16];
    int row = blockIdx.x;
    int tid = threadIdx.x;
    const float* xr = x + (size_t)row * D_;
    float v[3];
    #pragma unroll
    for (int i = 0; i < 3; i++) v[i] = xr[tid + i * 256];
    float sum = v[0] + v[1] + v[2];
    float sq = v[0] * v[0] + v[1] * v[1] + v[2] * v[2];
    block_sum2(sum, sq, sm);
    float mean = sum * (1.0f / D_);
    float var = sq * (1.0f / D_) - mean * mean;
    float r = rsqrtf(var + 1e-5f);
    __half* yr = y + (size_t)row * D_;
    #pragma unroll
    for (int i = 0; i < 3; i++) {
        int d = tid + i * 256;
        yr[d] = __float2half((v[i] - mean) * r * w[d] + bb[d]);
    }
}

// ---------------- attention: 32 queries per block, K/V tiled in smem --------
#define TQ_ 32
__global__ void __launch_bounds__(256) attn2_kernel() {
    __shared__ __align__(16) float Ks[64][68];
    __shared__ __align__(16) float sc[TQ_][200];
    int q0 = blockIdx.x * TQ_;
    int bh = blockIdx.y;
    int b = bh / H_, h = bh % H_;
    int tid = threadIdx.x;
    size_t base = (size_t)(b * SEQ_) * (3 * D_) + (size_t)h * HD_;

    // stage Q (scaled), then keep in registers
    float* Qtmp = &sc[0][0];
    for (int i = tid; i < TQ_ * 16; i += 256) {
        int r = i >> 4, j = i & 15;
        int srow = q0 + r;
        float4 v = make_float4(0.f, 0.f, 0.f, 0.f);
        if (srow < SEQ_)
            v = *(const float4*)(g_qkv + base + (size_t)srow * (3 * D_) + j * 4);
        v.x *= 0.125f; v.y *= 0.125f; v.z *= 0.125f; v.w *= 0.125f;
        *(float4*)(Qtmp + r * 64 + j * 4) = v;
    }
    __syncthreads();
    int q = tid >> 3, toff = tid & 7;
    float4 rq[16];
    #pragma unroll
    for (int j = 0; j < 16; j++) rq[j] = *(const float4*)(Qtmp + q * 64 + j * 4);
    __syncthreads();

    // scores
    for (int t0 = 0; t0 < SEQ_; t0 += 64) {
        int len = min(64, SEQ_ - t0);
        for (int i = tid; i < len * 16; i += 256) {
            int r = i >> 4, j = i & 15;
            float4 kv = *(const float4*)(g_qkv + base + D_ + (size_t)(t0 + r) * (3 * D_) + j * 4);
            *(float4*)(&Ks[r][j * 4]) = kv;
        }
        __syncthreads();
        for (int tt = toff; tt < len; tt += 8) {
            float a = 0.f;
            #pragma unroll
            for (int j = 0; j < 16; j++) {
                float4 kv = *(const float4*)(&Ks[tt][j * 4]);
                a += rq[j].x * kv.x + rq[j].y * kv.y + rq[j].z * kv.z + rq[j].w * kv.w;
            }
            sc[q][t0 + tt] = a;
        }
        __syncthreads();
    }

    // softmax: warp w handles 4 rows
    {
        int lane = tid & 31, w = tid >> 5;
        for (int r = w * 4; r < w * 4 + 4; r++) {
            float mx = -1e30f;
            for (int tt = lane; tt < SEQ_; tt += 32) mx = fmaxf(mx, sc[r][tt]);
            #pragma unroll
            for (int o = 16; o; o >>= 1) mx = fmaxf(mx, __shfl_xor_sync(0xffffffffu, mx, o));
            float s = 0.f;
            for (int tt = lane; tt < SEQ_; tt += 32) {
                float e = expf(sc[r][tt] - mx);
                sc[r][tt] = e;
                s += e;
            }
            #pragma unroll
            for (int o = 16; o; o >>= 1) s += __shfl_xor_sync(0xffffffffu, s, o);
            float inv = 1.0f / s;
            for (int tt = lane; tt < SEQ_; tt += 32) sc[r][tt] *= inv;
        }
    }
    __syncthreads();

    // o = p @ V  -> fp16 output
    int dg = tid & 7;
    float4 a0 = make_float4(0.f, 0.f, 0.f, 0.f);
    float4 a1 = make_float4(0.f, 0.f, 0.f, 0.f);
    for (int t0 = 0; t0 < SEQ_; t0 += 64) {
        int len = min(64, SEQ_ - t0);
        for (int i = tid; i < len * 16; i += 256) {
            int r = i >> 4, j = i & 15;
            float4 vv = *(const float4*)(g_qkv + base + 2 * D_ + (size_t)(t0 + r) * (3 * D_) + j * 4);
            *(float4*)(&Ks[r][j * 4]) = vv;
        }
        __syncthreads();
        for (int tt = 0; tt < len; tt++) {
            float p = sc[q][t0 + tt];
            float4 v0 = *(const float4*)(&Ks[tt][dg * 8]);
            float4 v1 = *(const float4*)(&Ks[tt][dg * 8 + 4]);
            a0.x += p * v0.x; a0.y += p * v0.y; a0.z += p * v0.z; a0.w += p * v0.w;
            a1.x += p * v1.x; a1.y += p * v1.y; a1.z += p * v1.z; a1.w += p * v1.w;
        }
        __syncthreads();
    }
    int srow = q0 + q;
    if (srow < SEQ_) {
        __half* o = g_att + (size_t)(b * SEQ_ + srow) * D_ + h * HD_ + dg * 8;
        uint4 u;
        u.x = h2_u32(__floats2half2_rn(a0.x, a0.y));
        u.y = h2_u32(__floats2half2_rn(a0.z, a0.w));
        u.z = h2_u32(__floats2half2_rn(a1.x, a1.y));
        u.w = h2_u32(__floats2half2_rn(a1.z, a1.w));
        *reinterpret_cast<uint4*>(o) = u;
    }
}

// ---------------- final head ----------------
__global__ void __launch_bounds__(256) head_kernel(
    const float* __restrict__ w, const float* __restrict__ bb,
    const float* __restrict__ proj, float* __restrict__ out)
{
    __shared__ float cls[D_];
    __shared__ float feats[E_];
    __shared__ float sm[16];
    int b = blockIdx.x;
    int tid = threadIdx.x;
    const float* xr = g_x + (size_t)(b * SEQ_) * D_;
    float v[3];
    #pragma unroll
    for (int i = 0; i < 3; i++) v[i] = xr[tid + i * 256];
    float sum = v[0] + v[1] + v[2];
    float sq = v[0] * v[0] + v[1] * v[1] + v[2] * v[2];
    block_sum2(sum, sq, sm);
    float mean = sum * (1.0f / D_);
    float var = sq * (1.0f / D_) - mean * mean;
    float r = rsqrtf(var + 1e-5f);
    #pragma unroll
    for (int i = 0; i < 3; i++) {
        int d = tid + i * 256;
        cls[d] = (v[i] - mean) * r * w[d] + bb[d];
    }
    __syncthreads();
    for (int e = tid; e < E_; e += 256) {
        float a = 0.f;
        for (int d = 0; d < D_; d++) a += cls[d] * proj[(size_t)d * E_ + e];
        feats[e] = a;
    }
    __syncthreads();
    float nrm = 0.f;
    for (int e = tid; e < E_; e += 256) nrm += feats[e] * feats[e];
    nrm = block_sum(nrm, sm);
    float rn = rsqrtf(nrm);
    for (int e = tid; e < E_; e += 256) out[(size_t)b * E_ + e] = feats[e] * rn;
}

// ---------------- host ----------------
extern "C" void kernel_launch(void* const* d_in, const int* in_sizes, int n_in,
                              void* d_out, int out_size)
{
    const float* image     = (const float*)d_in[0];
    const float* conv_w    = (const float*)d_in[1];
    const float* cls_emb   = (const float*)d_in[2];
    const float* pos_emb   = (const float*)d_in[3];
    const float* ln_pre_w  = (const float*)d_in[4];
    const float* ln_pre_b  = (const float*)d_in[5];
    const float* ln1_w     = (const float*)d_in[6];
    const float* ln1_b     = (const float*)d_in[7];
    const float* qkv_w     = (const float*)d_in[8];
    const float* qkv_b     = (const float*)d_in[9];
    const float* out_w     = (const float*)d_in[10];
    const float* out_b     = (const float*)d_in[11];
    const float* ln2_w     = (const float*)d_in[12];
    const float* ln2_b     = (const float*)d_in[13];
    const float* fc_w      = (const float*)d_in[14];
    const float* fc_b      = (const float*)d_in[15];
    const float* pr_w      = (const float*)d_in[16];
    const float* pr_b      = (const float*)d_in[17];
    const float* ln_post_w = (const float*)d_in[18];
    const float* ln_post_b = (const float*)d_in[19];
    const float* proj      = (const float*)d_in[20];
    float* out = (float*)d_out;
    (void)in_sizes; (void)n_in; (void)out_size;

    __half *p_patch, *p_ln, *p_att, *p_ff;
    float  *p_x, *p_qkv;
    __half *pw_qkv, *pw_out, *pw_fc, *pw_pr, *pw_conv;
    cudaGetSymbolAddress((void**)&p_patch, g_patch);
    cudaGetSymbolAddress((void**)&p_x,     g_x);
    cudaGetSymbolAddress((void**)&p_ln,    g_ln);
    cudaGetSymbolAddress((void**)&p_qkv,   g_qkv);
    cudaGetSymbolAddress((void**)&p_att,   g_att);
    cudaGetSymbolAddress((void**)&p_ff,    g_ff);
    cudaGetSymbolAddress((void**)&pw_qkv,  w_qkv);
    cudaGetSymbolAddress((void**)&pw_out,  w_out);
    cudaGetSymbolAddress((void**)&pw_fc,   w_fc);
    cudaGetSymbolAddress((void**)&pw_pr,   w_pr);
    cudaGetSymbolAddress((void**)&pw_conv, w_conv);

    cudaFuncSetAttribute(gemm_tc<0, false>, cudaFuncAttributeMaxDynamicSharedMemorySize, GSMEM_BYTES);
    cudaFuncSetAttribute(gemm_tc<1, false>, cudaFuncAttributeMaxDynamicSharedMemorySize, GSMEM_BYTES);
    cudaFuncSetAttribute(gemm_tc<2, true>,  cudaFuncAttributeMaxDynamicSharedMemorySize, GSMEM_BYTES);

    // fp16 weight copies
    auto cvt = [&](const float* s, __half* d, int n) {
        f2h_kernel<<<(n / 8 + 255) / 256, 256>>>((const float4*)s, d, n / 8);
    };
    cvt(qkv_w, pw_qkv, L_ * 3 * D_ * D_);
    cvt(out_w, pw_out, L_ * D_ * D_);
    cvt(fc_w,  pw_fc,  L_ * FF_ * D_);
    cvt(pr_w,  pw_pr,  L_ * D_ * FF_);
    cvt(conv_w, pw_conv, D_ * D_);

    const int MT = MP_ / 128;   // 50

    // patchify + conv-as-GEMM -> g_qkv (f32 scratch)
    patchify_kernel<<<(B_ * NP_ * D_ + 255) / 256, 256>>>(image);
    gemm_tc<0, false><<<dim3(MT, D_ / 128), 256, GSMEM_BYTES>>>(
        p_patch, pw_conv, nullptr, nullptr, p_qkv, D_, D_);
    embed_ln_kernel<<<NTOK, 256>>>(cls_emb, pos_emb, ln_pre_w, ln_pre_b);

    for (int l = 0; l < L_; l++) {
        ln_kernel<<<NTOK, 256>>>(p_x, p_ln, ln1_w + l * D_, ln1_b + l * D_);
        gemm_tc<0, false><<<dim3(MT, 3 * D_ / 128), 256, GSMEM_BYTES>>>(
            p_ln, pw_qkv + (size_t)l * 3 * D_ * D_, qkv_b + (size_t)l * 3 * D_,
            nullptr, p_qkv, 3 * D_, D_);
        attn2_kernel<<<dim3((SEQ_ + TQ_ - 1) / TQ_, B_ * H_), 256>>>();
        gemm_tc<1, false><<<dim3(MT, D_ / 128), 256, GSMEM_BYTES>>>(
            p_att, pw_out + (size_t)l * D_ * D_, out_b + (size_t)l * D_,
            p_x, p_x, D_, D_);
        ln_kernel<<<NTOK, 256>>>(p_x, p_ln, ln2_w + l * D_, ln2_b + l * D_);
        gemm_tc<2, true><<<dim3(MT, FF_ / 128), 256, GSMEM_BYTES>>>(
            p_ln, pw_fc + (size_t)l * FF_ * D_, fc_b + (size_t)l * FF_,
            nullptr, p_ff, FF_, D_);
        gemm_tc<1, false><<<dim3(MT, D_ / 128), 256, GSMEM_BYTES>>>(
            p_ff, pw_pr + (size_t)l * D_ * FF_, pr_b + (size_t)l * D_,
            p_x, p_x, D_, FF_);
    }
    head_kernel<<<B_, 256>>>(ln_post_w, ln_post_b, proj, out);
}